// round 11
// baseline (speedup 1.0000x reference)
#include <cuda_runtime.h>
#include <math.h>
#include <float.h>

#define BB 1024
#define LLN 50
#define EE 256
#define HH 256
#define KK2 512          // E + H
#define H4 1024
#define NEGV (-1e9f)
#define CEXPL 10.0f
#define KSPLIT 4
#define KSEG (KK2 / KSPLIT)   // 128

typedef unsigned long long u64;

// ---------------- device scratch (no allocations allowed) ----------------
__device__ __align__(16) float g_e_gl[(size_t)LLN * BB * HH];  // 52.4 MB
__device__ __align__(16) float g_e_pt[(size_t)LLN * BB * HH];  // 52.4 MB
__device__ __align__(16) float g_xh0[BB * KK2];                // [x | h] ping
__device__ __align__(16) float g_xh1[BB * KK2];                // [x | h] pong
__device__ __align__(16) float g_c  [BB * HH];
__device__ __align__(16) float g_qgl0[BB * HH];
__device__ __align__(16) float g_qgl1[BB * HH];
__device__ __align__(16) float g_g   [BB * HH];
__device__ __align__(16) float g_qpt0[BB * HH];
__device__ __align__(16) float g_qpt1[BB * HH];
__device__ __align__(16) float g_G  [(size_t)KSPLIT * BB * H4]; // split-K partials
__device__ __align__(16) float g_Wc [H4 * KK2];                // gate-interleaved [Wih|Whh]
__device__ __align__(16) float g_bc [H4];
__device__ __align__(16) float g_zero[H4];                     // static zero bias
__device__ unsigned char g_mask[BB * LLN];

// ---------------- packed fp32x2 FMA helpers (IEEE-exact) ------------------
__device__ __forceinline__ u64 pk2(float x, float y) {
    u64 r; asm("mov.b64 %0,{%1,%2};" : "=l"(r) : "f"(x), "f"(y)); return r;
}
__device__ __forceinline__ u64 pkdup(float x) {
    u64 r; asm("mov.b64 %0,{%1,%1};" : "=l"(r) : "f"(x)); return r;
}
__device__ __forceinline__ u64 ffma2(u64 a, u64 b, u64 c) {
    u64 d; asm("fma.rn.f32x2 %0,%1,%2,%3;" : "=l"(d) : "l"(a), "l"(b), "l"(c)); return d;
}
__device__ __forceinline__ float2 upk(u64 a) {
    float2 f; asm("mov.b64 {%0,%1},%2;" : "=f"(f.x), "=f"(f.y) : "l"(a)); return f;
}

// ---------------- FMA-pipe exp2 (deg-7 Horner, rel err ~1e-8) -------------
__device__ __forceinline__ float fexp2(float y) {
    float k = y + 12582912.0f;              // RN round-to-int via magic
    float f = y - (k - 12582912.0f);        // f in [-0.5, 0.5], exact
    float p =            1.5252734e-5f;
    p = fmaf(p, f, 1.5403530e-4f);
    p = fmaf(p, f, 1.3333558e-3f);
    p = fmaf(p, f, 9.6181291e-3f);
    p = fmaf(p, f, 5.5504109e-2f);
    p = fmaf(p, f, 2.4022651e-1f);
    p = fmaf(p, f, 6.9314718e-1f);
    p = fmaf(p, f, 1.0f);
    float sc = __int_as_float((__float_as_int(k) - 1262485377) << 23);
    return p * sc;
}

// tanh with 1 MUFU (rcp); rel err ~1e-7
__device__ __forceinline__ float fast_tanh(float x) {
    float ax = fabsf(x);
    float y  = fminf(ax * 2.8853901f, 126.0f);   // 2*log2(e)*ax
    float e2 = fexp2(y);
    float r  = 1.0f - __fdividef(2.0f, e2 + 1.0f);
    return copysignf(r, x);
}
__device__ __forceinline__ float sigm(float x) {
    float y = fminf(fmaxf(-x * 1.4426950f, -126.0f), 126.0f);
    return __fdividef(1.0f, 1.0f + fexp2(y));
}

// 4-term tanh-dot
__device__ __forceinline__ float tdot4(float4 q, float4 e, float4 v) {
    return fast_tanh(q.x + e.x) * v.x + fast_tanh(q.y + e.y) * v.y
         + fast_tanh(q.z + e.z) * v.z + fast_tanh(q.w + e.w) * v.w;
}

// ---------------- init ---------------------------------------------------
__global__ void k_init(const float* __restrict__ dec, const float* __restrict__ h0,
                       const float* __restrict__ c0) {
    int i = blockIdx.x * blockDim.x + threadIdx.x;
    if (i < BB * KK2) {
        int b = i >> 9, k = i & 511;
        g_xh0[i] = (k < EE) ? dec[b * EE + k] : h0[b * HH + (k - EE)];
    }
    if (i < BB * HH)  g_c[i] = c0[i];
    if (i < BB * LLN) g_mask[i] = 0;
}

// ---------------- weight prep (one-time) ----------------------------------
__global__ void k_prep_lstm(const float* __restrict__ Wih, const float* __restrict__ Whh,
                            const float* __restrict__ bih, const float* __restrict__ bhh) {
    int r = blockIdx.x;
    int j = r >> 2, g = r & 3;
    int src = g * HH + j;
    for (int k = threadIdx.x; k < EE; k += blockDim.x)
        g_Wc[(size_t)r * KK2 + k] = Wih[(size_t)src * EE + k];
    for (int k = threadIdx.x; k < HH; k += blockDim.x)
        g_Wc[(size_t)r * KK2 + EE + k] = Whh[(size_t)src * HH + k];
    if (threadIdx.x == 0) g_bc[r] = bih[src] + bhh[src];
}

// ---------------- generic NT GEMM with G->reg prefetch --------------------
struct GA { const float* A; int lda; const float* W; int wlda;
            const float* bias; float* C; };

template <int BM, int BN, int BK, int TM, int TN>
__global__ void gemm_multi(GA a0, GA a1, int N, int K) {
    constexpr int THREADS = (BM / TM) * (BN / TN);
    constexpr int A_LDS = BM * BK / THREADS / 4;
    constexpr int W_LDS = BN * BK / THREADS / 4;

    GA g = (blockIdx.z == 0) ? a0 : a1;

    __shared__ __align__(16) float As[BK][BM];
    __shared__ __align__(16) float Ws[BK][BN];

    const int tid = threadIdx.x;
    const int tx  = tid % (BN / TN);
    const int ty  = tid / (BN / TN);
    const int m0  = blockIdx.y * BM;
    const int n0  = blockIdx.x * BN;

    u64 acc[TM][TN / 2];
#pragma unroll
    for (int i = 0; i < TM; i++)
#pragma unroll
        for (int j = 0; j < TN / 2; j++) acc[i][j] = pk2(0.f, 0.f);

    float4 pa[A_LDS], pw[W_LDS];
#pragma unroll
    for (int i = 0; i < A_LDS; i++) {
        int li = tid + i * THREADS;
        pa[i] = *(const float4*)(g.A + (size_t)(m0 + li / (BK / 4)) * g.lda + (li % (BK / 4)) * 4);
    }
#pragma unroll
    for (int i = 0; i < W_LDS; i++) {
        int li = tid + i * THREADS;
        pw[i] = *(const float4*)(g.W + (size_t)(n0 + li / (BK / 4)) * g.wlda + (li % (BK / 4)) * 4);
    }

    for (int k0 = 0; k0 < K; k0 += BK) {
#pragma unroll
        for (int i = 0; i < A_LDS; i++) {
            int li = tid + i * THREADS;
            int r = li / (BK / 4), c4 = li % (BK / 4);
            As[c4 * 4 + 0][r] = pa[i].x; As[c4 * 4 + 1][r] = pa[i].y;
            As[c4 * 4 + 2][r] = pa[i].z; As[c4 * 4 + 3][r] = pa[i].w;
        }
#pragma unroll
        for (int i = 0; i < W_LDS; i++) {
            int li = tid + i * THREADS;
            int r = li / (BK / 4), c4 = li % (BK / 4);
            Ws[c4 * 4 + 0][r] = pw[i].x; Ws[c4 * 4 + 1][r] = pw[i].y;
            Ws[c4 * 4 + 2][r] = pw[i].z; Ws[c4 * 4 + 3][r] = pw[i].w;
        }
        __syncthreads();

        if (k0 + BK < K) {
#pragma unroll
            for (int i = 0; i < A_LDS; i++) {
                int li = tid + i * THREADS;
                pa[i] = *(const float4*)(g.A + (size_t)(m0 + li / (BK / 4)) * g.lda
                                         + k0 + BK + (li % (BK / 4)) * 4);
            }
#pragma unroll
            for (int i = 0; i < W_LDS; i++) {
                int li = tid + i * THREADS;
                pw[i] = *(const float4*)(g.W + (size_t)(n0 + li / (BK / 4)) * g.wlda
                                         + k0 + BK + (li % (BK / 4)) * 4);
            }
        }

#pragma unroll
        for (int kk = 0; kk < BK; kk++) {
            u64 bp[TN / 2];
#pragma unroll
            for (int j = 0; j < TN / 4; j++) {
                float4 wv = *(const float4*)&Ws[kk][tx * TN + j * 4];
                bp[2 * j]     = pk2(wv.x, wv.y);
                bp[2 * j + 1] = pk2(wv.z, wv.w);
            }
#pragma unroll
            for (int i = 0; i < TM; i += 4) {
                float4 av = *(const float4*)&As[kk][ty * TM + i];
                u64 q0 = pkdup(av.x), q1 = pkdup(av.y), q2 = pkdup(av.z), q3 = pkdup(av.w);
#pragma unroll
                for (int j = 0; j < TN / 2; j++) {
                    acc[i + 0][j] = ffma2(q0, bp[j], acc[i + 0][j]);
                    acc[i + 1][j] = ffma2(q1, bp[j], acc[i + 1][j]);
                    acc[i + 2][j] = ffma2(q2, bp[j], acc[i + 2][j]);
                    acc[i + 3][j] = ffma2(q3, bp[j], acc[i + 3][j]);
                }
            }
        }
        __syncthreads();
    }

    const int n = n0 + tx * TN;
    float bb[TN];
#pragma unroll
    for (int j = 0; j < TN; j++) bb[j] = g.bias[n + j];
#pragma unroll
    for (int i = 0; i < TM; i++) {
        int m = m0 + ty * TM + i;
#pragma unroll
        for (int j = 0; j < TN / 4; j++) {
            float2 u0 = upk(acc[i][2 * j]);
            float2 u1 = upk(acc[i][2 * j + 1]);
            float4 r;
            r.x = u0.x + bb[4 * j];     r.y = u0.y + bb[4 * j + 1];
            r.z = u1.x + bb[4 * j + 2]; r.w = u1.y + bb[4 * j + 3];
            *(float4*)(g.C + (size_t)m * N + n + 4 * j) = r;
        }
    }
}

// ---- LSTM gates split-K x4, BM128(batch)/BN64, TM8/TN8, 128 thr -----------
// grid (16, 8, 4) = 512 CTAs, 2048 warps; LDS/FMA = 2B/ffma2 (1.5x better than TN4).
__global__ void __launch_bounds__(128, 4) k_lstm4(const float* __restrict__ A0) {
    constexpr int BM = 128, BN = 64, BK = 16, TM = 8, TN = 8;
    constexpr int THREADS = 128;

    __shared__ __align__(16) float As[BK][BM];   // 8 KB
    __shared__ __align__(16) float Ws[BK][BN];   // 4 KB

    const int tid = threadIdx.x;
    const int tx  = tid % 8;            // BN/TN = 8
    const int ty  = tid / 8;            // 0..15
    const int m0  = blockIdx.y * BM;
    const int n0  = blockIdx.x * BN;
    const int z   = blockIdx.z;

    const float* A = A0 + z * KSEG;          // row stride KK2
    const float* W = g_Wc + z * KSEG;        // row stride KK2
    float* C = g_G + (size_t)z * BB * H4;

    u64 acc[TM][4];
#pragma unroll
    for (int i = 0; i < TM; i++)
#pragma unroll
        for (int j = 0; j < 4; j++) acc[i][j] = pk2(0.f, 0.f);

    float4 pa[4], pw[2];                 // A_LDS = 128*16/128/4 = 4 ; W_LDS = 2
#pragma unroll
    for (int i = 0; i < 4; i++) {
        int li = tid + i * THREADS;
        pa[i] = *(const float4*)(A + (size_t)(m0 + li / 4) * KK2 + (li % 4) * 4);
    }
#pragma unroll
    for (int i = 0; i < 2; i++) {
        int li = tid + i * THREADS;
        pw[i] = *(const float4*)(W + (size_t)(n0 + li / 4) * KK2 + (li % 4) * 4);
    }

    for (int k0 = 0; k0 < KSEG; k0 += BK) {
#pragma unroll
        for (int i = 0; i < 4; i++) {
            int li = tid + i * THREADS;
            int r = li / 4, c4 = li % 4;
            As[c4 * 4 + 0][r] = pa[i].x; As[c4 * 4 + 1][r] = pa[i].y;
            As[c4 * 4 + 2][r] = pa[i].z; As[c4 * 4 + 3][r] = pa[i].w;
        }
#pragma unroll
        for (int i = 0; i < 2; i++) {
            int li = tid + i * THREADS;
            int r = li / 4, c4 = li % 4;
            Ws[c4 * 4 + 0][r] = pw[i].x; Ws[c4 * 4 + 1][r] = pw[i].y;
            Ws[c4 * 4 + 2][r] = pw[i].z; Ws[c4 * 4 + 3][r] = pw[i].w;
        }
        __syncthreads();

        if (k0 + BK < KSEG) {
#pragma unroll
            for (int i = 0; i < 4; i++) {
                int li = tid + i * THREADS;
                pa[i] = *(const float4*)(A + (size_t)(m0 + li / 4) * KK2
                                         + k0 + BK + (li % 4) * 4);
            }
#pragma unroll
            for (int i = 0; i < 2; i++) {
                int li = tid + i * THREADS;
                pw[i] = *(const float4*)(W + (size_t)(n0 + li / 4) * KK2
                                         + k0 + BK + (li % 4) * 4);
            }
        }

#pragma unroll
        for (int kk = 0; kk < BK; kk++) {
            float4 w0 = *(const float4*)&Ws[kk][tx * TN];
            float4 w1 = *(const float4*)&Ws[kk][tx * TN + 4];
            u64 bp[4];
            bp[0] = pk2(w0.x, w0.y); bp[1] = pk2(w0.z, w0.w);
            bp[2] = pk2(w1.x, w1.y); bp[3] = pk2(w1.z, w1.w);
#pragma unroll
            for (int i = 0; i < TM; i += 4) {
                float4 av = *(const float4*)&As[kk][ty * TM + i];
                u64 q0 = pkdup(av.x), q1 = pkdup(av.y), q2 = pkdup(av.z), q3 = pkdup(av.w);
#pragma unroll
                for (int j = 0; j < 4; j++) {
                    acc[i + 0][j] = ffma2(q0, bp[j], acc[i + 0][j]);
                    acc[i + 1][j] = ffma2(q1, bp[j], acc[i + 1][j]);
                    acc[i + 2][j] = ffma2(q2, bp[j], acc[i + 2][j]);
                    acc[i + 3][j] = ffma2(q3, bp[j], acc[i + 3][j]);
                }
            }
        }
        __syncthreads();
    }

    const int n = n0 + tx * TN;
#pragma unroll
    for (int i = 0; i < TM; i++) {
        int m = m0 + ty * TM + i;
#pragma unroll
        for (int j = 0; j < 2; j++) {
            float2 u0 = upk(acc[i][2 * j]);
            float2 u1 = upk(acc[i][2 * j + 1]);
            float4 r; r.x = u0.x; r.y = u0.y; r.z = u1.x; r.w = u1.y;
            *(float4*)(C + (size_t)m * H4 + n + 4 * j) = r;
        }
    }
}

// ---------------- LSTM cell: sum 4 split-K partials + nonlinearity ---------
__global__ void k_cell(float* __restrict__ xh_next) {
    int b = blockIdx.x, j = threadIdx.x;          // 1024 x 256
    size_t off = (size_t)b * H4 + 4 * j;
    const float4 p0 = *(const float4*)(g_G + off);
    const float4 p1 = *(const float4*)(g_G + (size_t)1 * BB * H4 + off);
    const float4 p2 = *(const float4*)(g_G + (size_t)2 * BB * H4 + off);
    const float4 p3 = *(const float4*)(g_G + (size_t)3 * BB * H4 + off);
    const float4 bc = *(const float4*)(g_bc + 4 * j);
    float gi = (p0.x + p1.x) + (p2.x + p3.x) + bc.x;
    float gf = (p0.y + p1.y) + (p2.y + p3.y) + bc.y;
    float gg = (p0.z + p1.z) + (p2.z + p3.z) + bc.z;
    float go = (p0.w + p1.w) + (p2.w + p3.w) + bc.w;
    float c  = g_c[(size_t)b * HH + j];
    float c2 = sigm(gf) * c + sigm(gi) * fast_tanh(gg);
    g_c[(size_t)b * HH + j] = c2;
    xh_next[(size_t)b * KK2 + EE + j] = sigm(go) * fast_tanh(c2);
}

// ------ glimpse attention: batched-load u-pass, softmax, combine -> g ------
__global__ void k_attn_gl(const float* __restrict__ v) {
    int b = blockIdx.x, tid = threadIdx.x, lane = tid & 31, w = tid >> 5;
    __shared__ __align__(16) float qs[HH], vs[HH];
    __shared__ float sp[LLN];
    __shared__ float s_inv;
    qs[tid] = g_qgl0[(size_t)b * HH + tid] + g_qgl1[(size_t)b * HH + tid];
    vs[tid] = v[tid];
    __syncthreads();

    const float* eb = g_e_gl + (size_t)b * HH;
    float4 q0 = ((const float4*)qs)[lane * 2], q1 = ((const float4*)qs)[lane * 2 + 1];
    float4 v0 = ((const float4*)vs)[lane * 2], v1 = ((const float4*)vs)[lane * 2 + 1];

    float s[7];
    float4 ebuf[7];
#pragma unroll
    for (int i = 0; i < 7; i++) {                 // batch 7 independent L2 loads
        int l = w + 8 * i; int lc = (l < LLN) ? l : (LLN - 1);
        ebuf[i] = ((const float4*)(eb + (size_t)lc * BB * HH))[lane * 2];
    }
#pragma unroll
    for (int i = 0; i < 7; i++) s[i] = tdot4(q0, ebuf[i], v0);
#pragma unroll
    for (int i = 0; i < 7; i++) {
        int l = w + 8 * i; int lc = (l < LLN) ? l : (LLN - 1);
        ebuf[i] = ((const float4*)(eb + (size_t)lc * BB * HH))[lane * 2 + 1];
    }
#pragma unroll
    for (int i = 0; i < 7; i++) s[i] += tdot4(q1, ebuf[i], v1);
#pragma unroll
    for (int o = 16; o; o >>= 1)
#pragma unroll
        for (int i = 0; i < 7; i++) s[i] += __shfl_xor_sync(0xffffffffu, s[i], o);
    if (lane == 0) {
#pragma unroll
        for (int i = 0; i < 7; i++) {
            int l = w + 8 * i;
            if (l < LLN) sp[l] = g_mask[b * LLN + l] ? NEGV : s[i];
        }
    }
    __syncthreads();
    if (w == 0) {
        float a  = (lane < LLN) ? sp[lane] : -FLT_MAX;
        float bb = (lane + 32 < LLN) ? sp[lane + 32] : -FLT_MAX;
        float m = fmaxf(a, bb);
#pragma unroll
        for (int o = 16; o; o >>= 1) m = fmaxf(m, __shfl_xor_sync(0xffffffffu, m, o));
        float ea  = (lane < LLN) ? __expf(a - m) : 0.f;
        float eb2 = (lane + 32 < LLN) ? __expf(bb - m) : 0.f;
        if (lane < LLN) sp[lane] = ea;
        if (lane + 32 < LLN) sp[lane + 32] = eb2;
        float ssum = ea + eb2;
#pragma unroll
        for (int o = 16; o; o >>= 1) ssum += __shfl_xor_sync(0xffffffffu, ssum, o);
        if (lane == 0) s_inv = __fdividef(1.f, ssum);
    }
    __syncthreads();
    float inv = s_inv;
    const float* ec = eb + tid;
    float a0 = 0.f, a1 = 0.f;
#pragma unroll
    for (int l = 0; l < LLN; l += 2) {
        a0 = fmaf(sp[l],     ec[(size_t) l      * BB * HH], a0);
        a1 = fmaf(sp[l + 1], ec[(size_t)(l + 1) * BB * HH], a1);
    }
    g_g[(size_t)b * HH + tid] = (a0 + a1) * inv;
}

// ---- pointer attention: log_softmax (-> out), argmax, gather, mask --------
__global__ void k_attn_pt(const float* __restrict__ v, const float* __restrict__ emb,
                          float* __restrict__ out, float* __restrict__ sel_out,
                          int t, int wsel, float* __restrict__ xh_next) {
    int b = blockIdx.x, tid = threadIdx.x, lane = tid & 31, w = tid >> 5;
    __shared__ __align__(16) float qs[HH], vs[HH];
    __shared__ float sp[LLN];
    __shared__ float s_lse;
    __shared__ int s_idx;
    qs[tid] = g_qpt0[(size_t)b * HH + tid] + g_qpt1[(size_t)b * HH + tid];
    vs[tid] = v[tid];
    __syncthreads();

    const float* eb = g_e_pt + (size_t)b * HH;
    float4 q0 = ((const float4*)qs)[lane * 2], q1 = ((const float4*)qs)[lane * 2 + 1];
    float4 v0 = ((const float4*)vs)[lane * 2], v1 = ((const float4*)vs)[lane * 2 + 1];

    float s[7];
    float4 ebuf[7];
#pragma unroll
    for (int i = 0; i < 7; i++) {
        int l = w + 8 * i; int lc = (l < LLN) ? l : (LLN - 1);
        ebuf[i] = ((const float4*)(eb + (size_t)lc * BB * HH))[lane * 2];
    }
#pragma unroll
    for (int i = 0; i < 7; i++) s[i] = tdot4(q0, ebuf[i], v0);
#pragma unroll
    for (int i = 0; i < 7; i++) {
        int l = w + 8 * i; int lc = (l < LLN) ? l : (LLN - 1);
        ebuf[i] = ((const float4*)(eb + (size_t)lc * BB * HH))[lane * 2 + 1];
    }
#pragma unroll
    for (int i = 0; i < 7; i++) s[i] += tdot4(q1, ebuf[i], v1);
#pragma unroll
    for (int o = 16; o; o >>= 1)
#pragma unroll
        for (int i = 0; i < 7; i++) s[i] += __shfl_xor_sync(0xffffffffu, s[i], o);
    if (lane == 0) {
#pragma unroll
        for (int i = 0; i < 7; i++) {
            int l = w + 8 * i;
            if (l < LLN) sp[l] = g_mask[b * LLN + l] ? NEGV : (CEXPL * fast_tanh(s[i]));
        }
    }
    __syncthreads();
    if (w == 0) {
        float a  = (lane < LLN) ? sp[lane] : -FLT_MAX;           int ia = lane;
        float bb = (lane + 32 < LLN) ? sp[lane + 32] : -FLT_MAX; int ib = lane + 32;
        float m; int mi;
        if (bb > a) { m = bb; mi = ib; } else { m = a; mi = ia; }
#pragma unroll
        for (int o = 16; o; o >>= 1) {
            float om = __shfl_xor_sync(0xffffffffu, m, o);
            int   oi = __shfl_xor_sync(0xffffffffu, mi, o);
            if (om > m || (om == m && oi < mi)) { m = om; mi = oi; }
        }
        float ssum = ((lane < LLN) ? __expf(a - m) : 0.f)
                   + ((lane + 32 < LLN) ? __expf(bb - m) : 0.f);
#pragma unroll
        for (int o = 16; o; o >>= 1) ssum += __shfl_xor_sync(0xffffffffu, ssum, o);
        if (lane == 0) { s_lse = m + __logf(ssum); s_idx = mi; }
    }
    __syncthreads();
    int idx = s_idx; float lse = s_lse;
    if (tid < LLN)
        out[((size_t)b * LLN + t) * LLN + tid] = sp[tid] - lse;
    xh_next[(size_t)b * KK2 + tid] = emb[((size_t)idx * BB + b) * EE + tid];
    if (tid == 0) {
        g_mask[b * LLN + idx] = 1;       // mask for NEXT step
        int cnt = 0;
#pragma unroll
        for (int l = 0; l < LLN; l++) cnt += g_mask[b * LLN + l];
        if (cnt == LLN) g_mask[b * LLN + LLN - 1] = 0;   // ref's all-true reset
        if (wsel) sel_out[b * LLN + t] = (float)idx;
    }
}

// -------------------------------- launch ----------------------------------
extern "C" void kernel_launch(void* const* d_in, const int* in_sizes, int n_in,
                              void* d_out, int out_size) {
    (void)in_sizes; (void)n_in;
    const float* dec  = (const float*)d_in[0];
    const float* emb  = (const float*)d_in[1];
    const float* h0   = (const float*)d_in[2];
    const float* c0   = (const float*)d_in[3];
    const float* ctx  = (const float*)d_in[4];
    const float* Wih  = (const float*)d_in[6];
    const float* Whh  = (const float*)d_in[7];
    const float* bih  = (const float*)d_in[8];
    const float* bhh  = (const float*)d_in[9];
    const float* glWq = (const float*)d_in[10];
    const float* glbq = (const float*)d_in[11];
    const float* glWr = (const float*)d_in[12];
    const float* glbr = (const float*)d_in[13];
    const float* glv  = (const float*)d_in[14];
    const float* ptWq = (const float*)d_in[15];
    const float* ptbq = (const float*)d_in[16];
    const float* ptWr = (const float*)d_in[17];
    const float* ptbr = (const float*)d_in[18];
    const float* ptv  = (const float*)d_in[19];
    float* out = (float*)d_out;

    float *pe_gl, *pe_pt, *pxh0, *pxh1, *pg, *pzero;
    float *pqgl0, *pqgl1, *pqpt0, *pqpt1;
    cudaGetSymbolAddress((void**)&pe_gl, g_e_gl);
    cudaGetSymbolAddress((void**)&pe_pt, g_e_pt);
    cudaGetSymbolAddress((void**)&pxh0,  g_xh0);
    cudaGetSymbolAddress((void**)&pxh1,  g_xh1);
    cudaGetSymbolAddress((void**)&pg,    g_g);
    cudaGetSymbolAddress((void**)&pzero, g_zero);
    cudaGetSymbolAddress((void**)&pqgl0, g_qgl0);
    cudaGetSymbolAddress((void**)&pqgl1, g_qgl1);
    cudaGetSymbolAddress((void**)&pqpt0, g_qpt0);
    cudaGetSymbolAddress((void**)&pqpt1, g_qpt1);

    k_init<<<2048, 256>>>(dec, h0, c0);
    k_prep_lstm<<<H4, 256>>>(Wih, Whh, bih, bhh);

    // Time-invariant projections (z=2): e_gl = ctx@glWr^T+glbr ; e_pt = ctx@ptWr^T+ptbr
    {
        GA a0{ctx, HH, glWr, HH, glbr, pe_gl};
        GA a1{ctx, HH, ptWr, HH, ptbr, pe_pt};
        dim3 g(HH / 128, (LLN * BB) / 128, 2);
        gemm_multi<128, 128, 16, 8, 8><<<g, 256>>>(a0, a1, HH, HH);
    }

    const size_t BLLL = (size_t)BB * LLN * LLN;
    const int wsel = (out_size >= (int)(BLLL + (size_t)BB * LLN)) ? 1 : 0;

    float* xh[2] = {pxh0, pxh1};
    for (int t = 0; t < LLN; t++) {
        float* cur = xh[t & 1];
        float* nxt = xh[(t + 1) & 1];
        // LSTM gates split-K x4, TM8xTN8 tile -> g_G[0..3]; 512 CTAs of 128 thr
        k_lstm4<<<dim3(H4 / 64, BB / 128, KSPLIT), 128>>>(cur);
        // cell: sum partials, nonlinearity, h_t -> nxt[:,256:512]
        k_cell<<<BB, HH>>>(nxt);
        // q_gl split-K x2 (bias in z=0; partials summed in k_attn_gl)
        {
            GA a0{nxt + EE,       KK2, glWq,       HH, glbq,  pqgl0};
            GA a1{nxt + EE + 128, KK2, glWq + 128, HH, pzero, pqgl1};
            gemm_multi<32, 64, 16, 4, 4><<<dim3(HH / 64, BB / 32, 2), 128>>>(a0, a1, HH, 128);
        }
        // glimpse attention -> g
        k_attn_gl<<<BB, HH>>>(glv);
        // q_pt split-K x2
        {
            GA a0{pg,       HH, ptWq,       HH, ptbq,  pqpt0};
            GA a1{pg + 128, HH, ptWq + 128, HH, pzero, pqpt1};
            gemm_multi<32, 64, 16, 4, 4><<<dim3(HH / 64, BB / 32, 2), 128>>>(a0, a1, HH, 128);
        }
        // pointer attention: log_p -> out, argmax, gather x_{t+1}, mask update
        k_attn_pt<<<BB, HH>>>(ptv, emb, out, out + BLLL, t, wsel, nxt);
    }
}

// round 12
// speedup vs baseline: 1.0928x; 1.0928x over previous
#include <cuda_runtime.h>
#include <math.h>
#include <float.h>

#define BB 1024
#define LLN 50
#define EE 256
#define HH 256
#define KK2 512          // E + H
#define H4 1024
#define NEGV (-1e9f)
#define CEXPL 10.0f
#define KSPLIT 4
#define KSEG (KK2 / KSPLIT)   // 128

typedef unsigned long long u64;

// ---------------- device scratch (no allocations allowed) ----------------
__device__ __align__(16) float g_e_gl[(size_t)LLN * BB * HH];  // 52.4 MB
__device__ __align__(16) float g_e_pt[(size_t)LLN * BB * HH];  // 52.4 MB
__device__ __align__(16) float g_xh0[BB * KK2];                // [x | h] ping
__device__ __align__(16) float g_xh1[BB * KK2];                // [x | h] pong
__device__ __align__(16) float g_c  [BB * HH];
__device__ __align__(16) float g_qgl0[BB * HH];
__device__ __align__(16) float g_qgl1[BB * HH];
__device__ __align__(16) float g_g   [BB * HH];
__device__ __align__(16) float g_qpt0[BB * HH];
__device__ __align__(16) float g_qpt1[BB * HH];
__device__ __align__(16) float g_G  [(size_t)KSPLIT * BB * H4]; // split-K partials
__device__ __align__(16) float g_Wc [H4 * KK2];                // gate-interleaved [Wih|Whh]
__device__ __align__(16) float g_bc [H4];
__device__ __align__(16) float g_zero[H4];                     // static zero bias
__device__ unsigned char g_mask[BB * LLN];

// ---------------- packed fp32x2 helpers (IEEE-exact per lane) -------------
__device__ __forceinline__ u64 pk2(float x, float y) {
    u64 r; asm("mov.b64 %0,{%1,%2};" : "=l"(r) : "f"(x), "f"(y)); return r;
}
__device__ __forceinline__ u64 pkdup(float x) {
    u64 r; asm("mov.b64 %0,{%1,%1};" : "=l"(r) : "f"(x)); return r;
}
__device__ __forceinline__ u64 ffma2(u64 a, u64 b, u64 c) {
    u64 d; asm("fma.rn.f32x2 %0,%1,%2,%3;" : "=l"(d) : "l"(a), "l"(b), "l"(c)); return d;
}
__device__ __forceinline__ u64 fmul2(u64 a, u64 b) {
    u64 d; asm("mul.rn.f32x2 %0,%1,%2;" : "=l"(d) : "l"(a), "l"(b)); return d;
}
__device__ __forceinline__ u64 fadd2(u64 a, u64 b) {
    u64 d; asm("add.rn.f32x2 %0,%1,%2;" : "=l"(d) : "l"(a), "l"(b)); return d;
}
__device__ __forceinline__ float2 upk(u64 a) {
    float2 f; asm("mov.b64 {%0,%1},%2;" : "=f"(f.x), "=f"(f.y) : "l"(a)); return f;
}

// ---------------- FMA-pipe exp2 (deg-7 Horner, rel err ~1e-8) -------------
__device__ __forceinline__ float fexp2(float y) {
    float k = y + 12582912.0f;              // RN round-to-int via magic
    float f = y - (k - 12582912.0f);        // f in [-0.5, 0.5], exact
    float p =            1.5252734e-5f;
    p = fmaf(p, f, 1.5403530e-4f);
    p = fmaf(p, f, 1.3333558e-3f);
    p = fmaf(p, f, 9.6181291e-3f);
    p = fmaf(p, f, 5.5504109e-2f);
    p = fmaf(p, f, 2.4022651e-1f);
    p = fmaf(p, f, 6.9314718e-1f);
    p = fmaf(p, f, 1.0f);
    float sc = __int_as_float((__float_as_int(k) - 1262485377) << 23);
    return p * sc;
}

// scalar tanh (used outside hot loop); rel err ~1e-7
__device__ __forceinline__ float fast_tanh(float x) {
    float ax = fabsf(x);
    float y  = fminf(ax * 2.8853901f, 126.0f);   // 2*log2(e)*ax
    float e2 = fexp2(y);
    float r  = 1.0f - __fdividef(2.0f, e2 + 1.0f);
    return copysignf(r, x);
}
__device__ __forceinline__ float sigm(float x) {
    float y = fminf(fmaxf(-x * 1.4426950f, -126.0f), 126.0f);
    return __fdividef(1.0f, 1.0f + fexp2(y));
}

// ---- 2-way packed tanh: tanh(x) = 1 - 2/(1 + 2^(2*log2(e)*x)), signed ----
// Packed deg-6 exp2 Horner (rel err ~1.2e-7 -> tanh abs err ~6e-8).
// Per-element exponent via clamped int construct: handles saturation safely.
__device__ __forceinline__ void tanh2(float x0, float x1, float& r0, float& r1) {
    const u64 C2  = pkdup(2.8853901f);        // 2*log2(e)
    const u64 M2  = pkdup(12582912.0f);
    const u64 N1  = pkdup(-1.0f);
    u64 x2 = pk2(x0, x1);
    u64 xc = fmul2(x2, C2);
    u64 k2 = fadd2(xc, M2);
    u64 nf = fadd2(k2, pkdup(-12582912.0f));  // n as float
    u64 f2 = ffma2(nf, N1, xc);               // f = xc - n, in [-0.5, 0.5]
    u64 p  = ffma2(f2, pkdup(1.5403530e-4f), pkdup(1.3333558e-3f));
    p = ffma2(p, f2, pkdup(9.6181291e-3f));
    p = ffma2(p, f2, pkdup(5.5504109e-2f));
    p = ffma2(p, f2, pkdup(2.4022651e-1f));
    p = ffma2(p, f2, pkdup(6.9314718e-1f));
    p = ffma2(p, f2, pkdup(1.0f));
    float2 kk = upk(k2);
    float2 pp = upk(p);
    // element 0: biased exponent m = bits(k) - (0x4B400000 - 127), clamp [0,255]
    int m0 = __float_as_int(kk.x) - 1262485377;
    m0 = max(0, min(m0, 255));
    float e0 = pp.x * __int_as_float(m0 << 23);
    float d0 = e0 + 1.0f;
    float i0; asm("rcp.approx.f32 %0,%1;" : "=f"(i0) : "f"(d0));
    r0 = fmaf(-2.0f, i0, 1.0f);
    // element 1
    int m1 = __float_as_int(kk.y) - 1262485377;
    m1 = max(0, min(m1, 255));
    float e1 = pp.y * __int_as_float(m1 << 23);
    float d1 = e1 + 1.0f;
    float i1; asm("rcp.approx.f32 %0,%1;" : "=f"(i1) : "f"(d1));
    r1 = fmaf(-2.0f, i1, 1.0f);
}

// 4-term tanh-dot using packed tanh pairs
__device__ __forceinline__ float tdot4(float4 q, float4 e, float4 v) {
    float t0, t1, t2, t3;
    tanh2(q.x + e.x, q.y + e.y, t0, t1);
    tanh2(q.z + e.z, q.w + e.w, t2, t3);
    return fmaf(t0, v.x, fmaf(t1, v.y, fmaf(t2, v.z, t3 * v.w)));
}

// ---------------- init ---------------------------------------------------
__global__ void k_init(const float* __restrict__ dec, const float* __restrict__ h0,
                       const float* __restrict__ c0) {
    int i = blockIdx.x * blockDim.x + threadIdx.x;
    if (i < BB * KK2) {
        int b = i >> 9, k = i & 511;
        g_xh0[i] = (k < EE) ? dec[b * EE + k] : h0[b * HH + (k - EE)];
    }
    if (i < BB * HH)  g_c[i] = c0[i];
    if (i < BB * LLN) g_mask[i] = 0;
}

// ---------------- weight prep (one-time) ----------------------------------
__global__ void k_prep_lstm(const float* __restrict__ Wih, const float* __restrict__ Whh,
                            const float* __restrict__ bih, const float* __restrict__ bhh) {
    int r = blockIdx.x;
    int j = r >> 2, g = r & 3;
    int src = g * HH + j;
    for (int k = threadIdx.x; k < EE; k += blockDim.x)
        g_Wc[(size_t)r * KK2 + k] = Wih[(size_t)src * EE + k];
    for (int k = threadIdx.x; k < HH; k += blockDim.x)
        g_Wc[(size_t)r * KK2 + EE + k] = Whh[(size_t)src * HH + k];
    if (threadIdx.x == 0) g_bc[r] = bih[src] + bhh[src];
}

// ---------------- generic NT GEMM with G->reg prefetch --------------------
struct GA { const float* A; int lda; const float* W; int wlda;
            const float* bias; float* C; };

template <int BM, int BN, int BK, int TM, int TN>
__global__ void gemm_multi(GA a0, GA a1, int N, int K) {
    constexpr int THREADS = (BM / TM) * (BN / TN);
    constexpr int A_LDS = BM * BK / THREADS / 4;
    constexpr int W_LDS = BN * BK / THREADS / 4;

    GA g = (blockIdx.z == 0) ? a0 : a1;

    __shared__ __align__(16) float As[BK][BM];
    __shared__ __align__(16) float Ws[BK][BN];

    const int tid = threadIdx.x;
    const int tx  = tid % (BN / TN);
    const int ty  = tid / (BN / TN);
    const int m0  = blockIdx.y * BM;
    const int n0  = blockIdx.x * BN;

    u64 acc[TM][TN / 2];
#pragma unroll
    for (int i = 0; i < TM; i++)
#pragma unroll
        for (int j = 0; j < TN / 2; j++) acc[i][j] = pk2(0.f, 0.f);

    float4 pa[A_LDS], pw[W_LDS];
#pragma unroll
    for (int i = 0; i < A_LDS; i++) {
        int li = tid + i * THREADS;
        pa[i] = *(const float4*)(g.A + (size_t)(m0 + li / (BK / 4)) * g.lda + (li % (BK / 4)) * 4);
    }
#pragma unroll
    for (int i = 0; i < W_LDS; i++) {
        int li = tid + i * THREADS;
        pw[i] = *(const float4*)(g.W + (size_t)(n0 + li / (BK / 4)) * g.wlda + (li % (BK / 4)) * 4);
    }

    for (int k0 = 0; k0 < K; k0 += BK) {
#pragma unroll
        for (int i = 0; i < A_LDS; i++) {
            int li = tid + i * THREADS;
            int r = li / (BK / 4), c4 = li % (BK / 4);
            As[c4 * 4 + 0][r] = pa[i].x; As[c4 * 4 + 1][r] = pa[i].y;
            As[c4 * 4 + 2][r] = pa[i].z; As[c4 * 4 + 3][r] = pa[i].w;
        }
#pragma unroll
        for (int i = 0; i < W_LDS; i++) {
            int li = tid + i * THREADS;
            int r = li / (BK / 4), c4 = li % (BK / 4);
            Ws[c4 * 4 + 0][r] = pw[i].x; Ws[c4 * 4 + 1][r] = pw[i].y;
            Ws[c4 * 4 + 2][r] = pw[i].z; Ws[c4 * 4 + 3][r] = pw[i].w;
        }
        __syncthreads();

        if (k0 + BK < K) {
#pragma unroll
            for (int i = 0; i < A_LDS; i++) {
                int li = tid + i * THREADS;
                pa[i] = *(const float4*)(g.A + (size_t)(m0 + li / (BK / 4)) * g.lda
                                         + k0 + BK + (li % (BK / 4)) * 4);
            }
#pragma unroll
            for (int i = 0; i < W_LDS; i++) {
                int li = tid + i * THREADS;
                pw[i] = *(const float4*)(g.W + (size_t)(n0 + li / (BK / 4)) * g.wlda
                                         + k0 + BK + (li % (BK / 4)) * 4);
            }
        }

#pragma unroll
        for (int kk = 0; kk < BK; kk++) {
            u64 bp[TN / 2];
#pragma unroll
            for (int j = 0; j < TN / 4; j++) {
                float4 wv = *(const float4*)&Ws[kk][tx * TN + j * 4];
                bp[2 * j]     = pk2(wv.x, wv.y);
                bp[2 * j + 1] = pk2(wv.z, wv.w);
            }
#pragma unroll
            for (int i = 0; i < TM; i += 4) {
                float4 av = *(const float4*)&As[kk][ty * TM + i];
                u64 q0 = pkdup(av.x), q1 = pkdup(av.y), q2 = pkdup(av.z), q3 = pkdup(av.w);
#pragma unroll
                for (int j = 0; j < TN / 2; j++) {
                    acc[i + 0][j] = ffma2(q0, bp[j], acc[i + 0][j]);
                    acc[i + 1][j] = ffma2(q1, bp[j], acc[i + 1][j]);
                    acc[i + 2][j] = ffma2(q2, bp[j], acc[i + 2][j]);
                    acc[i + 3][j] = ffma2(q3, bp[j], acc[i + 3][j]);
                }
            }
        }
        __syncthreads();
    }

    const int n = n0 + tx * TN;
    float bb[TN];
#pragma unroll
    for (int j = 0; j < TN; j++) bb[j] = g.bias[n + j];
#pragma unroll
    for (int i = 0; i < TM; i++) {
        int m = m0 + ty * TM + i;
#pragma unroll
        for (int j = 0; j < TN / 4; j++) {
            float2 u0 = upk(acc[i][2 * j]);
            float2 u1 = upk(acc[i][2 * j + 1]);
            float4 r;
            r.x = u0.x + bb[4 * j];     r.y = u0.y + bb[4 * j + 1];
            r.z = u1.x + bb[4 * j + 2]; r.w = u1.y + bb[4 * j + 3];
            *(float4*)(g.C + (size_t)m * N + n + 4 * j) = r;
        }
    }
}

// ---------------- LSTM gates, split-K x4 (R7-proven config) ----------------
// BM=64, BN=64, BK=16, TM=8, TN=4, 128 thr; grid (16,16,4) = 1024 CTAs.
__global__ void k_lstm4(const float* __restrict__ A0) {
    constexpr int BM = 64, BN = 64, BK = 16, TM = 8;
    constexpr int THREADS = 128;

    __shared__ __align__(16) float As[BK][BM];
    __shared__ __align__(16) float Ws[BK][BN];

    const int tid = threadIdx.x;
    const int tx  = tid % 16;           // BN/TN
    const int ty  = tid / 16;
    const int m0  = blockIdx.y * BM;
    const int n0  = blockIdx.x * BN;
    const int z   = blockIdx.z;

    const float* A = A0 + z * KSEG;          // row stride KK2
    const float* W = g_Wc + z * KSEG;        // row stride KK2
    float* C = g_G + (size_t)z * BB * H4;

    u64 acc[TM][2];
#pragma unroll
    for (int i = 0; i < TM; i++) { acc[i][0] = pk2(0.f, 0.f); acc[i][1] = pk2(0.f, 0.f); }

    float4 pa[2], pw[2];                 // A_LDS = W_LDS = 2
#pragma unroll
    for (int i = 0; i < 2; i++) {
        int li = tid + i * THREADS;
        pa[i] = *(const float4*)(A + (size_t)(m0 + li / 4) * KK2 + (li % 4) * 4);
        pw[i] = *(const float4*)(W + (size_t)(n0 + li / 4) * KK2 + (li % 4) * 4);
    }

    for (int k0 = 0; k0 < KSEG; k0 += BK) {
#pragma unroll
        for (int i = 0; i < 2; i++) {
            int li = tid + i * THREADS;
            int r = li / 4, c4 = li % 4;
            As[c4 * 4 + 0][r] = pa[i].x; As[c4 * 4 + 1][r] = pa[i].y;
            As[c4 * 4 + 2][r] = pa[i].z; As[c4 * 4 + 3][r] = pa[i].w;
            Ws[c4 * 4 + 0][r] = pw[i].x; Ws[c4 * 4 + 1][r] = pw[i].y;
            Ws[c4 * 4 + 2][r] = pw[i].z; Ws[c4 * 4 + 3][r] = pw[i].w;
        }
        __syncthreads();

        if (k0 + BK < KSEG) {
#pragma unroll
            for (int i = 0; i < 2; i++) {
                int li = tid + i * THREADS;
                pa[i] = *(const float4*)(A + (size_t)(m0 + li / 4) * KK2
                                         + k0 + BK + (li % 4) * 4);
                pw[i] = *(const float4*)(W + (size_t)(n0 + li / 4) * KK2
                                         + k0 + BK + (li % 4) * 4);
            }
        }

#pragma unroll
        for (int kk = 0; kk < BK; kk++) {
            float4 bv = *(const float4*)&Ws[kk][tx * 4];
            u64 bp0 = pk2(bv.x, bv.y);
            u64 bp1 = pk2(bv.z, bv.w);
#pragma unroll
            for (int i = 0; i < TM; i += 4) {
                float4 av = *(const float4*)&As[kk][ty * TM + i];
                u64 q0 = pkdup(av.x), q1 = pkdup(av.y), q2 = pkdup(av.z), q3 = pkdup(av.w);
                acc[i + 0][0] = ffma2(q0, bp0, acc[i + 0][0]);
                acc[i + 0][1] = ffma2(q0, bp1, acc[i + 0][1]);
                acc[i + 1][0] = ffma2(q1, bp0, acc[i + 1][0]);
                acc[i + 1][1] = ffma2(q1, bp1, acc[i + 1][1]);
                acc[i + 2][0] = ffma2(q2, bp0, acc[i + 2][0]);
                acc[i + 2][1] = ffma2(q2, bp1, acc[i + 2][1]);
                acc[i + 3][0] = ffma2(q3, bp0, acc[i + 3][0]);
                acc[i + 3][1] = ffma2(q3, bp1, acc[i + 3][1]);
            }
        }
        __syncthreads();
    }

    const int n = n0 + tx * 4;
#pragma unroll
    for (int i = 0; i < TM; i++) {
        int m = m0 + ty * TM + i;
        float2 u0 = upk(acc[i][0]);
        float2 u1 = upk(acc[i][1]);
        float4 r; r.x = u0.x; r.y = u0.y; r.z = u1.x; r.w = u1.y;
        *(float4*)(C + (size_t)m * H4 + n) = r;
    }
}

// ---------------- LSTM cell: sum 4 split-K partials + nonlinearity ---------
__global__ void k_cell(float* __restrict__ xh_next) {
    int b = blockIdx.x, j = threadIdx.x;          // 1024 x 256
    size_t off = (size_t)b * H4 + 4 * j;
    const float4 p0 = *(const float4*)(g_G + off);
    const float4 p1 = *(const float4*)(g_G + (size_t)1 * BB * H4 + off);
    const float4 p2 = *(const float4*)(g_G + (size_t)2 * BB * H4 + off);
    const float4 p3 = *(const float4*)(g_G + (size_t)3 * BB * H4 + off);
    const float4 bc = *(const float4*)(g_bc + 4 * j);
    float gi = (p0.x + p1.x) + (p2.x + p3.x) + bc.x;
    float gf = (p0.y + p1.y) + (p2.y + p3.y) + bc.y;
    float gg = (p0.z + p1.z) + (p2.z + p3.z) + bc.z;
    float go = (p0.w + p1.w) + (p2.w + p3.w) + bc.w;
    float c  = g_c[(size_t)b * HH + j];
    float c2 = sigm(gf) * c + sigm(gi) * fast_tanh(gg);
    g_c[(size_t)b * HH + j] = c2;
    xh_next[(size_t)b * KK2 + EE + j] = sigm(go) * fast_tanh(c2);
}

// ------ glimpse attention: batched-load u-pass, softmax, combine -> g ------
__global__ void k_attn_gl(const float* __restrict__ v) {
    int b = blockIdx.x, tid = threadIdx.x, lane = tid & 31, w = tid >> 5;
    __shared__ __align__(16) float qs[HH], vs[HH];
    __shared__ float sp[LLN];
    __shared__ float s_inv;
    qs[tid] = g_qgl0[(size_t)b * HH + tid] + g_qgl1[(size_t)b * HH + tid];
    vs[tid] = v[tid];
    __syncthreads();

    const float* eb = g_e_gl + (size_t)b * HH;
    float4 q0 = ((const float4*)qs)[lane * 2], q1 = ((const float4*)qs)[lane * 2 + 1];
    float4 v0 = ((const float4*)vs)[lane * 2], v1 = ((const float4*)vs)[lane * 2 + 1];

    float s[7];
    float4 ebuf[7];
#pragma unroll
    for (int i = 0; i < 7; i++) {                 // batch 7 independent L2 loads
        int l = w + 8 * i; int lc = (l < LLN) ? l : (LLN - 1);
        ebuf[i] = ((const float4*)(eb + (size_t)lc * BB * HH))[lane * 2];
    }
#pragma unroll
    for (int i = 0; i < 7; i++) s[i] = tdot4(q0, ebuf[i], v0);
#pragma unroll
    for (int i = 0; i < 7; i++) {
        int l = w + 8 * i; int lc = (l < LLN) ? l : (LLN - 1);
        ebuf[i] = ((const float4*)(eb + (size_t)lc * BB * HH))[lane * 2 + 1];
    }
#pragma unroll
    for (int i = 0; i < 7; i++) s[i] += tdot4(q1, ebuf[i], v1);
#pragma unroll
    for (int o = 16; o; o >>= 1)
#pragma unroll
        for (int i = 0; i < 7; i++) s[i] += __shfl_xor_sync(0xffffffffu, s[i], o);
    if (lane == 0) {
#pragma unroll
        for (int i = 0; i < 7; i++) {
            int l = w + 8 * i;
            if (l < LLN) sp[l] = g_mask[b * LLN + l] ? NEGV : s[i];
        }
    }
    __syncthreads();
    if (w == 0) {
        float a  = (lane < LLN) ? sp[lane] : -FLT_MAX;
        float bb = (lane + 32 < LLN) ? sp[lane + 32] : -FLT_MAX;
        float m = fmaxf(a, bb);
#pragma unroll
        for (int o = 16; o; o >>= 1) m = fmaxf(m, __shfl_xor_sync(0xffffffffu, m, o));
        float ea  = (lane < LLN) ? __expf(a - m) : 0.f;
        float eb2 = (lane + 32 < LLN) ? __expf(bb - m) : 0.f;
        if (lane < LLN) sp[lane] = ea;
        if (lane + 32 < LLN) sp[lane + 32] = eb2;
        float ssum = ea + eb2;
#pragma unroll
        for (int o = 16; o; o >>= 1) ssum += __shfl_xor_sync(0xffffffffu, ssum, o);
        if (lane == 0) s_inv = __fdividef(1.f, ssum);
    }
    __syncthreads();
    float inv = s_inv;
    const float* ec = eb + tid;
    float a0 = 0.f, a1 = 0.f;
#pragma unroll
    for (int l = 0; l < LLN; l += 2) {
        a0 = fmaf(sp[l],     ec[(size_t) l      * BB * HH], a0);
        a1 = fmaf(sp[l + 1], ec[(size_t)(l + 1) * BB * HH], a1);
    }
    g_g[(size_t)b * HH + tid] = (a0 + a1) * inv;
}

// ---- pointer attention: log_softmax (-> out), argmax, gather, mask --------
__global__ void k_attn_pt(const float* __restrict__ v, const float* __restrict__ emb,
                          float* __restrict__ out, float* __restrict__ sel_out,
                          int t, int wsel, float* __restrict__ xh_next) {
    int b = blockIdx.x, tid = threadIdx.x, lane = tid & 31, w = tid >> 5;
    __shared__ __align__(16) float qs[HH], vs[HH];
    __shared__ float sp[LLN];
    __shared__ float s_lse;
    __shared__ int s_idx;
    qs[tid] = g_qpt0[(size_t)b * HH + tid] + g_qpt1[(size_t)b * HH + tid];
    vs[tid] = v[tid];
    __syncthreads();

    const float* eb = g_e_pt + (size_t)b * HH;
    float4 q0 = ((const float4*)qs)[lane * 2], q1 = ((const float4*)qs)[lane * 2 + 1];
    float4 v0 = ((const float4*)vs)[lane * 2], v1 = ((const float4*)vs)[lane * 2 + 1];

    float s[7];
    float4 ebuf[7];
#pragma unroll
    for (int i = 0; i < 7; i++) {
        int l = w + 8 * i; int lc = (l < LLN) ? l : (LLN - 1);
        ebuf[i] = ((const float4*)(eb + (size_t)lc * BB * HH))[lane * 2];
    }
#pragma unroll
    for (int i = 0; i < 7; i++) s[i] = tdot4(q0, ebuf[i], v0);
#pragma unroll
    for (int i = 0; i < 7; i++) {
        int l = w + 8 * i; int lc = (l < LLN) ? l : (LLN - 1);
        ebuf[i] = ((const float4*)(eb + (size_t)lc * BB * HH))[lane * 2 + 1];
    }
#pragma unroll
    for (int i = 0; i < 7; i++) s[i] += tdot4(q1, ebuf[i], v1);
#pragma unroll
    for (int o = 16; o; o >>= 1)
#pragma unroll
        for (int i = 0; i < 7; i++) s[i] += __shfl_xor_sync(0xffffffffu, s[i], o);
    if (lane == 0) {
#pragma unroll
        for (int i = 0; i < 7; i++) {
            int l = w + 8 * i;
            if (l < LLN) sp[l] = g_mask[b * LLN + l] ? NEGV : (CEXPL * fast_tanh(s[i]));
        }
    }
    __syncthreads();
    if (w == 0) {
        float a  = (lane < LLN) ? sp[lane] : -FLT_MAX;           int ia = lane;
        float bb = (lane + 32 < LLN) ? sp[lane + 32] : -FLT_MAX; int ib = lane + 32;
        float m; int mi;
        if (bb > a) { m = bb; mi = ib; } else { m = a; mi = ia; }
#pragma unroll
        for (int o = 16; o; o >>= 1) {
            float om = __shfl_xor_sync(0xffffffffu, m, o);
            int   oi = __shfl_xor_sync(0xffffffffu, mi, o);
            if (om > m || (om == m && oi < mi)) { m = om; mi = oi; }
        }
        float ssum = ((lane < LLN) ? __expf(a - m) : 0.f)
                   + ((lane + 32 < LLN) ? __expf(bb - m) : 0.f);
#pragma unroll
        for (int o = 16; o; o >>= 1) ssum += __shfl_xor_sync(0xffffffffu, ssum, o);
        if (lane == 0) { s_lse = m + __logf(ssum); s_idx = mi; }
    }
    __syncthreads();
    int idx = s_idx; float lse = s_lse;
    if (tid < LLN)
        out[((size_t)b * LLN + t) * LLN + tid] = sp[tid] - lse;
    xh_next[(size_t)b * KK2 + tid] = emb[((size_t)idx * BB + b) * EE + tid];
    if (tid == 0) {
        g_mask[b * LLN + idx] = 1;       // mask for NEXT step
        int cnt = 0;
#pragma unroll
        for (int l = 0; l < LLN; l++) cnt += g_mask[b * LLN + l];
        if (cnt == LLN) g_mask[b * LLN + LLN - 1] = 0;   // ref's all-true reset
        if (wsel) sel_out[b * LLN + t] = (float)idx;
    }
}

// -------------------------------- launch ----------------------------------
extern "C" void kernel_launch(void* const* d_in, const int* in_sizes, int n_in,
                              void* d_out, int out_size) {
    (void)in_sizes; (void)n_in;
    const float* dec  = (const float*)d_in[0];
    const float* emb  = (const float*)d_in[1];
    const float* h0   = (const float*)d_in[2];
    const float* c0   = (const float*)d_in[3];
    const float* ctx  = (const float*)d_in[4];
    const float* Wih  = (const float*)d_in[6];
    const float* Whh  = (const float*)d_in[7];
    const float* bih  = (const float*)d_in[8];
    const float* bhh  = (const float*)d_in[9];
    const float* glWq = (const float*)d_in[10];
    const float* glbq = (const float*)d_in[11];
    const float* glWr = (const float*)d_in[12];
    const float* glbr = (const float*)d_in[13];
    const float* glv  = (const float*)d_in[14];
    const float* ptWq = (const float*)d_in[15];
    const float* ptbq = (const float*)d_in[16];
    const float* ptWr = (const float*)d_in[17];
    const float* ptbr = (const float*)d_in[18];
    const float* ptv  = (const float*)d_in[19];
    float* out = (float*)d_out;

    float *pe_gl, *pe_pt, *pxh0, *pxh1, *pg, *pzero;
    float *pqgl0, *pqgl1, *pqpt0, *pqpt1;
    cudaGetSymbolAddress((void**)&pe_gl, g_e_gl);
    cudaGetSymbolAddress((void**)&pe_pt, g_e_pt);
    cudaGetSymbolAddress((void**)&pxh0,  g_xh0);
    cudaGetSymbolAddress((void**)&pxh1,  g_xh1);
    cudaGetSymbolAddress((void**)&pg,    g_g);
    cudaGetSymbolAddress((void**)&pzero, g_zero);
    cudaGetSymbolAddress((void**)&pqgl0, g_qgl0);
    cudaGetSymbolAddress((void**)&pqgl1, g_qgl1);
    cudaGetSymbolAddress((void**)&pqpt0, g_qpt0);
    cudaGetSymbolAddress((void**)&pqpt1, g_qpt1);

    k_init<<<2048, 256>>>(dec, h0, c0);
    k_prep_lstm<<<H4, 256>>>(Wih, Whh, bih, bhh);

    // Time-invariant projections (z=2): e_gl = ctx@glWr^T+glbr ; e_pt = ctx@ptWr^T+ptbr
    {
        GA a0{ctx, HH, glWr, HH, glbr, pe_gl};
        GA a1{ctx, HH, ptWr, HH, ptbr, pe_pt};
        dim3 g(HH / 128, (LLN * BB) / 128, 2);
        gemm_multi<128, 128, 16, 8, 8><<<g, 256>>>(a0, a1, HH, HH);
    }

    const size_t BLLL = (size_t)BB * LLN * LLN;
    const int wsel = (out_size >= (int)(BLLL + (size_t)BB * LLN)) ? 1 : 0;

    float* xh[2] = {pxh0, pxh1};
    for (int t = 0; t < LLN; t++) {
        float* cur = xh[t & 1];
        float* nxt = xh[(t + 1) & 1];
        // LSTM gates, split-K x4 -> g_G[0..3]; 1024 CTAs of 128 thr (R7 config)
        k_lstm4<<<dim3(H4 / 64, BB / 64, KSPLIT), 128>>>(cur);
        // cell: sum partials, nonlinearity, h_t -> nxt[:,256:512]
        k_cell<<<BB, HH>>>(nxt);
        // q_gl split-K x2 (bias in z=0; partials summed in k_attn_gl)
        {
            GA a0{nxt + EE,       KK2, glWq,       HH, glbq,  pqgl0};
            GA a1{nxt + EE + 128, KK2, glWq + 128, HH, pzero, pqgl1};
            gemm_multi<32, 64, 16, 4, 4><<<dim3(HH / 64, BB / 32, 2), 128>>>(a0, a1, HH, 128);
        }
        // glimpse attention -> g
        k_attn_gl<<<BB, HH>>>(glv);
        // q_pt split-K x2
        {
            GA a0{pg,       HH, ptWq,       HH, ptbq,  pqpt0};
            GA a1{pg + 128, HH, ptWq + 128, HH, pzero, pqpt1};
            gemm_multi<32, 64, 16, 4, 4><<<dim3(HH / 64, BB / 32, 2), 128>>>(a0, a1, HH, 128);
        }
        // pointer attention: log_p -> out, argmax, gather x_{t+1}, mask update
        k_attn_pt<<<BB, HH>>>(ptv, emb, out, out + BLLL, t, wsel, nxt);
    }
}

// round 13
// speedup vs baseline: 1.1430x; 1.0460x over previous
#include <cuda_runtime.h>
#include <math.h>
#include <float.h>

#define BB 1024
#define LLN 50
#define EE 256
#define HH 256
#define KK2 512          // E + H
#define H4 1024
#define NEGV (-1e9f)
#define CEXPL 10.0f
#define KSPLIT 4
#define KSEG (KK2 / KSPLIT)   // 128

typedef unsigned long long u64;

// ---------------- device scratch (no allocations allowed) ----------------
// After k_exp transform, g_e_gl / g_e_pt hold exp(2*e), not e.
__device__ __align__(16) float g_e_gl[(size_t)LLN * BB * HH];  // 52.4 MB
__device__ __align__(16) float g_e_pt[(size_t)LLN * BB * HH];  // 52.4 MB
__device__ __align__(16) float g_xh0[BB * KK2];                // [x | h] ping
__device__ __align__(16) float g_xh1[BB * KK2];                // [x | h] pong
__device__ __align__(16) float g_c  [BB * HH];
__device__ __align__(16) float g_qgl0[BB * HH];
__device__ __align__(16) float g_qgl1[BB * HH];
__device__ __align__(16) float g_g   [BB * HH];
__device__ __align__(16) float g_qpt0[BB * HH];
__device__ __align__(16) float g_qpt1[BB * HH];
__device__ __align__(16) float g_G  [(size_t)KSPLIT * BB * H4]; // split-K partials
__device__ __align__(16) float g_Wc [H4 * KK2];                // gate-interleaved [Wih|Whh]
__device__ __align__(16) float g_bc [H4];
__device__ __align__(16) float g_zero[H4];                     // static zero bias
__device__ unsigned char g_mask[BB * LLN];

// ---------------- packed fp32x2 helpers (IEEE-exact per lane) -------------
__device__ __forceinline__ u64 pk2(float x, float y) {
    u64 r; asm("mov.b64 %0,{%1,%2};" : "=l"(r) : "f"(x), "f"(y)); return r;
}
__device__ __forceinline__ u64 pkdup(float x) {
    u64 r; asm("mov.b64 %0,{%1,%1};" : "=l"(r) : "f"(x)); return r;
}
__device__ __forceinline__ u64 ffma2(u64 a, u64 b, u64 c) {
    u64 d; asm("fma.rn.f32x2 %0,%1,%2,%3;" : "=l"(d) : "l"(a), "l"(b), "l"(c)); return d;
}
__device__ __forceinline__ float2 upk(u64 a) {
    float2 f; asm("mov.b64 {%0,%1},%2;" : "=f"(f.x), "=f"(f.y) : "l"(a)); return f;
}
__device__ __forceinline__ float frcp(float x) {
    float r; asm("rcp.approx.f32 %0,%1;" : "=f"(r) : "f"(x)); return r;
}

// ---------------- FMA-pipe exp2 (deg-7 Horner, rel err ~1e-8) -------------
__device__ __forceinline__ float fexp2(float y) {
    float k = y + 12582912.0f;              // RN round-to-int via magic
    float f = y - (k - 12582912.0f);        // f in [-0.5, 0.5], exact
    float p =            1.5252734e-5f;
    p = fmaf(p, f, 1.5403530e-4f);
    p = fmaf(p, f, 1.3333558e-3f);
    p = fmaf(p, f, 9.6181291e-3f);
    p = fmaf(p, f, 5.5504109e-2f);
    p = fmaf(p, f, 2.4022651e-1f);
    p = fmaf(p, f, 6.9314718e-1f);
    p = fmaf(p, f, 1.0f);
    float sc = __int_as_float((__float_as_int(k) - 1262485377) << 23);
    return p * sc;
}

// exp(2x), clamped to finite fp32 range
__device__ __forceinline__ float fexp2e(float x) {
    float y = fminf(fmaxf(x * 2.8853901f, -126.0f), 126.0f);  // 2*log2(e)*x
    return fexp2(y);
}

// scalar tanh (cell + pointer logits); rel err ~1e-7
__device__ __forceinline__ float fast_tanh(float x) {
    float ax = fabsf(x);
    float y  = fminf(ax * 2.8853901f, 126.0f);
    float e2 = fexp2(y);
    float r  = 1.0f - __fdividef(2.0f, e2 + 1.0f);
    return copysignf(r, x);
}
__device__ __forceinline__ float sigm(float x) {
    float y = fminf(fmaxf(-x * 1.4426950f, -126.0f), 126.0f);
    return __fdividef(1.0f, 1.0f + fexp2(y));
}

// ---------------- init ---------------------------------------------------
__global__ void k_init(const float* __restrict__ dec, const float* __restrict__ h0,
                       const float* __restrict__ c0) {
    int i = blockIdx.x * blockDim.x + threadIdx.x;
    if (i < BB * KK2) {
        int b = i >> 9, k = i & 511;
        g_xh0[i] = (k < EE) ? dec[b * EE + k] : h0[b * HH + (k - EE)];
    }
    if (i < BB * HH)  g_c[i] = c0[i];
    if (i < BB * LLN) g_mask[i] = 0;
}

// ---------------- weight prep (one-time) ----------------------------------
__global__ void k_prep_lstm(const float* __restrict__ Wih, const float* __restrict__ Whh,
                            const float* __restrict__ bih, const float* __restrict__ bhh) {
    int r = blockIdx.x;
    int j = r >> 2, g = r & 3;
    int src = g * HH + j;
    for (int k = threadIdx.x; k < EE; k += blockDim.x)
        g_Wc[(size_t)r * KK2 + k] = Wih[(size_t)src * EE + k];
    for (int k = threadIdx.x; k < HH; k += blockDim.x)
        g_Wc[(size_t)r * KK2 + EE + k] = Whh[(size_t)src * HH + k];
    if (threadIdx.x == 0) g_bc[r] = bih[src] + bhh[src];
}

// ---------------- in-place transform: e -> exp(2e) -------------------------
__global__ void k_exp() {
    size_t i = (size_t)blockIdx.x * blockDim.x + threadIdx.x;   // float4 index
    float4* p = (blockIdx.y == 0) ? (float4*)g_e_gl : (float4*)g_e_pt;
    float4 v = p[i];
    v.x = fexp2e(v.x); v.y = fexp2e(v.y); v.z = fexp2e(v.z); v.w = fexp2e(v.w);
    p[i] = v;
}

// ---------------- generic NT GEMM with G->reg prefetch --------------------
struct GA { const float* A; int lda; const float* W; int wlda;
            const float* bias; float* C; };

template <int BM, int BN, int BK, int TM, int TN>
__global__ void gemm_multi(GA a0, GA a1, int N, int K) {
    constexpr int THREADS = (BM / TM) * (BN / TN);
    constexpr int A_LDS = BM * BK / THREADS / 4;
    constexpr int W_LDS = BN * BK / THREADS / 4;

    GA g = (blockIdx.z == 0) ? a0 : a1;

    __shared__ __align__(16) float As[BK][BM];
    __shared__ __align__(16) float Ws[BK][BN];

    const int tid = threadIdx.x;
    const int tx  = tid % (BN / TN);
    const int ty  = tid / (BN / TN);
    const int m0  = blockIdx.y * BM;
    const int n0  = blockIdx.x * BN;

    u64 acc[TM][TN / 2];
#pragma unroll
    for (int i = 0; i < TM; i++)
#pragma unroll
        for (int j = 0; j < TN / 2; j++) acc[i][j] = pk2(0.f, 0.f);

    float4 pa[A_LDS], pw[W_LDS];
#pragma unroll
    for (int i = 0; i < A_LDS; i++) {
        int li = tid + i * THREADS;
        pa[i] = *(const float4*)(g.A + (size_t)(m0 + li / (BK / 4)) * g.lda + (li % (BK / 4)) * 4);
    }
#pragma unroll
    for (int i = 0; i < W_LDS; i++) {
        int li = tid + i * THREADS;
        pw[i] = *(const float4*)(g.W + (size_t)(n0 + li / (BK / 4)) * g.wlda + (li % (BK / 4)) * 4);
    }

    for (int k0 = 0; k0 < K; k0 += BK) {
#pragma unroll
        for (int i = 0; i < A_LDS; i++) {
            int li = tid + i * THREADS;
            int r = li / (BK / 4), c4 = li % (BK / 4);
            As[c4 * 4 + 0][r] = pa[i].x; As[c4 * 4 + 1][r] = pa[i].y;
            As[c4 * 4 + 2][r] = pa[i].z; As[c4 * 4 + 3][r] = pa[i].w;
        }
#pragma unroll
        for (int i = 0; i < W_LDS; i++) {
            int li = tid + i * THREADS;
            int r = li / (BK / 4), c4 = li % (BK / 4);
            Ws[c4 * 4 + 0][r] = pw[i].x; Ws[c4 * 4 + 1][r] = pw[i].y;
            Ws[c4 * 4 + 2][r] = pw[i].z; Ws[c4 * 4 + 3][r] = pw[i].w;
        }
        __syncthreads();

        if (k0 + BK < K) {
#pragma unroll
            for (int i = 0; i < A_LDS; i++) {
                int li = tid + i * THREADS;
                pa[i] = *(const float4*)(g.A + (size_t)(m0 + li / (BK / 4)) * g.lda
                                         + k0 + BK + (li % (BK / 4)) * 4);
            }
#pragma unroll
            for (int i = 0; i < W_LDS; i++) {
                int li = tid + i * THREADS;
                pw[i] = *(const float4*)(g.W + (size_t)(n0 + li / (BK / 4)) * g.wlda
                                         + k0 + BK + (li % (BK / 4)) * 4);
            }
        }

#pragma unroll
        for (int kk = 0; kk < BK; kk++) {
            u64 bp[TN / 2];
#pragma unroll
            for (int j = 0; j < TN / 4; j++) {
                float4 wv = *(const float4*)&Ws[kk][tx * TN + j * 4];
                bp[2 * j]     = pk2(wv.x, wv.y);
                bp[2 * j + 1] = pk2(wv.z, wv.w);
            }
#pragma unroll
            for (int i = 0; i < TM; i += 4) {
                float4 av = *(const float4*)&As[kk][ty * TM + i];
                u64 q0 = pkdup(av.x), q1 = pkdup(av.y), q2 = pkdup(av.z), q3 = pkdup(av.w);
#pragma unroll
                for (int j = 0; j < TN / 2; j++) {
                    acc[i + 0][j] = ffma2(q0, bp[j], acc[i + 0][j]);
                    acc[i + 1][j] = ffma2(q1, bp[j], acc[i + 1][j]);
                    acc[i + 2][j] = ffma2(q2, bp[j], acc[i + 2][j]);
                    acc[i + 3][j] = ffma2(q3, bp[j], acc[i + 3][j]);
                }
            }
        }
        __syncthreads();
    }

    const int n = n0 + tx * TN;
    float bb[TN];
#pragma unroll
    for (int j = 0; j < TN; j++) bb[j] = g.bias[n + j];
#pragma unroll
    for (int i = 0; i < TM; i++) {
        int m = m0 + ty * TM + i;
#pragma unroll
        for (int j = 0; j < TN / 4; j++) {
            float2 u0 = upk(acc[i][2 * j]);
            float2 u1 = upk(acc[i][2 * j + 1]);
            float4 r;
            r.x = u0.x + bb[4 * j];     r.y = u0.y + bb[4 * j + 1];
            r.z = u1.x + bb[4 * j + 2]; r.w = u1.y + bb[4 * j + 3];
            *(float4*)(g.C + (size_t)m * N + n + 4 * j) = r;
        }
    }
}

// ---------------- LSTM gates, split-K x4 (R7-proven config) ----------------
__global__ void k_lstm4(const float* __restrict__ A0) {
    constexpr int BM = 64, BN = 64, BK = 16, TM = 8;
    constexpr int THREADS = 128;

    __shared__ __align__(16) float As[BK][BM];
    __shared__ __align__(16) float Ws[BK][BN];

    const int tid = threadIdx.x;
    const int tx  = tid % 16;           // BN/TN
    const int ty  = tid / 16;
    const int m0  = blockIdx.y * BM;
    const int n0  = blockIdx.x * BN;
    const int z   = blockIdx.z;

    const float* A = A0 + z * KSEG;          // row stride KK2
    const float* W = g_Wc + z * KSEG;        // row stride KK2
    float* C = g_G + (size_t)z * BB * H4;

    u64 acc[TM][2];
#pragma unroll
    for (int i = 0; i < TM; i++) { acc[i][0] = pk2(0.f, 0.f); acc[i][1] = pk2(0.f, 0.f); }

    float4 pa[2], pw[2];
#pragma unroll
    for (int i = 0; i < 2; i++) {
        int li = tid + i * THREADS;
        pa[i] = *(const float4*)(A + (size_t)(m0 + li / 4) * KK2 + (li % 4) * 4);
        pw[i] = *(const float4*)(W + (size_t)(n0 + li / 4) * KK2 + (li % 4) * 4);
    }

    for (int k0 = 0; k0 < KSEG; k0 += BK) {
#pragma unroll
        for (int i = 0; i < 2; i++) {
            int li = tid + i * THREADS;
            int r = li / 4, c4 = li % 4;
            As[c4 * 4 + 0][r] = pa[i].x; As[c4 * 4 + 1][r] = pa[i].y;
            As[c4 * 4 + 2][r] = pa[i].z; As[c4 * 4 + 3][r] = pa[i].w;
            Ws[c4 * 4 + 0][r] = pw[i].x; Ws[c4 * 4 + 1][r] = pw[i].y;
            Ws[c4 * 4 + 2][r] = pw[i].z; Ws[c4 * 4 + 3][r] = pw[i].w;
        }
        __syncthreads();

        if (k0 + BK < KSEG) {
#pragma unroll
            for (int i = 0; i < 2; i++) {
                int li = tid + i * THREADS;
                pa[i] = *(const float4*)(A + (size_t)(m0 + li / 4) * KK2
                                         + k0 + BK + (li % 4) * 4);
                pw[i] = *(const float4*)(W + (size_t)(n0 + li / 4) * KK2
                                         + k0 + BK + (li % 4) * 4);
            }
        }

#pragma unroll
        for (int kk = 0; kk < BK; kk++) {
            float4 bv = *(const float4*)&Ws[kk][tx * 4];
            u64 bp0 = pk2(bv.x, bv.y);
            u64 bp1 = pk2(bv.z, bv.w);
#pragma unroll
            for (int i = 0; i < TM; i += 4) {
                float4 av = *(const float4*)&As[kk][ty * TM + i];
                u64 q0 = pkdup(av.x), q1 = pkdup(av.y), q2 = pkdup(av.z), q3 = pkdup(av.w);
                acc[i + 0][0] = ffma2(q0, bp0, acc[i + 0][0]);
                acc[i + 0][1] = ffma2(q0, bp1, acc[i + 0][1]);
                acc[i + 1][0] = ffma2(q1, bp0, acc[i + 1][0]);
                acc[i + 1][1] = ffma2(q1, bp1, acc[i + 1][1]);
                acc[i + 2][0] = ffma2(q2, bp0, acc[i + 2][0]);
                acc[i + 2][1] = ffma2(q2, bp1, acc[i + 2][1]);
                acc[i + 3][0] = ffma2(q3, bp0, acc[i + 3][0]);
                acc[i + 3][1] = ffma2(q3, bp1, acc[i + 3][1]);
            }
        }
        __syncthreads();
    }

    const int n = n0 + tx * 4;
#pragma unroll
    for (int i = 0; i < TM; i++) {
        int m = m0 + ty * TM + i;
        float2 u0 = upk(acc[i][0]);
        float2 u1 = upk(acc[i][1]);
        float4 r; r.x = u0.x; r.y = u0.y; r.z = u1.x; r.w = u1.y;
        *(float4*)(C + (size_t)m * H4 + n) = r;
    }
}

// ---------------- LSTM cell: sum 4 split-K partials + nonlinearity ---------
__global__ void k_cell(float* __restrict__ xh_next) {
    int b = blockIdx.x, j = threadIdx.x;          // 1024 x 256
    size_t off = (size_t)b * H4 + 4 * j;
    const float4 p0 = *(const float4*)(g_G + off);
    const float4 p1 = *(const float4*)(g_G + (size_t)1 * BB * H4 + off);
    const float4 p2 = *(const float4*)(g_G + (size_t)2 * BB * H4 + off);
    const float4 p3 = *(const float4*)(g_G + (size_t)3 * BB * H4 + off);
    const float4 bc = *(const float4*)(g_bc + 4 * j);
    float gi = (p0.x + p1.x) + (p2.x + p3.x) + bc.x;
    float gf = (p0.y + p1.y) + (p2.y + p3.y) + bc.y;
    float gg = (p0.z + p1.z) + (p2.z + p3.z) + bc.z;
    float go = (p0.w + p1.w) + (p2.w + p3.w) + bc.w;
    float c  = g_c[(size_t)b * HH + j];
    float c2 = sigm(gf) * c + sigm(gi) * fast_tanh(gg);
    g_c[(size_t)b * HH + j] = c2;
    xh_next[(size_t)b * KK2 + EE + j] = sigm(go) * fast_tanh(c2);
}

// ------ glimpse attention: exp-form u-pass, softmax, log-combine -> g ------
// E = exp(2e) stored; tanh(q+e) = 1 - 2/(1 + exp(2q)*E)
// u = Sv - 2 * sum_h v_h / (1 + Q_h * E_h)
__global__ void k_attn_gl(const float* __restrict__ v) {
    int b = blockIdx.x, tid = threadIdx.x, lane = tid & 31, w = tid >> 5;
    __shared__ __align__(16) float qs[HH], vs[HH];
    __shared__ float sp[LLN];
    __shared__ float s_inv;
    qs[tid] = g_qgl0[(size_t)b * HH + tid] + g_qgl1[(size_t)b * HH + tid];
    vs[tid] = v[tid];
    __syncthreads();

    const float* eb = g_e_gl + (size_t)b * HH;
    float4 Q0 = ((const float4*)qs)[lane * 2], Q1 = ((const float4*)qs)[lane * 2 + 1];
    Q0.x = fexp2e(Q0.x); Q0.y = fexp2e(Q0.y); Q0.z = fexp2e(Q0.z); Q0.w = fexp2e(Q0.w);
    Q1.x = fexp2e(Q1.x); Q1.y = fexp2e(Q1.y); Q1.z = fexp2e(Q1.z); Q1.w = fexp2e(Q1.w);
    float4 v0 = ((const float4*)vs)[lane * 2], v1 = ((const float4*)vs)[lane * 2 + 1];
    float sv = ((v0.x + v0.y) + (v0.z + v0.w)) + ((v1.x + v1.y) + (v1.z + v1.w));
#pragma unroll
    for (int o = 16; o; o >>= 1) sv += __shfl_xor_sync(0xffffffffu, sv, o);

    float s[7];
    float4 ebuf[7];
#pragma unroll
    for (int i = 0; i < 7; i++) {                 // batch 7 independent L2 loads
        int l = w + 8 * i; int lc = (l < LLN) ? l : (LLN - 1);
        ebuf[i] = ((const float4*)(eb + (size_t)lc * BB * HH))[lane * 2];
    }
#pragma unroll
    for (int i = 0; i < 7; i++) {
        float r;
        r = frcp(fmaf(Q0.x, ebuf[i].x, 1.f)); s[i] = v0.x * r;
        r = frcp(fmaf(Q0.y, ebuf[i].y, 1.f)); s[i] = fmaf(v0.y, r, s[i]);
        r = frcp(fmaf(Q0.z, ebuf[i].z, 1.f)); s[i] = fmaf(v0.z, r, s[i]);
        r = frcp(fmaf(Q0.w, ebuf[i].w, 1.f)); s[i] = fmaf(v0.w, r, s[i]);
    }
#pragma unroll
    for (int i = 0; i < 7; i++) {
        int l = w + 8 * i; int lc = (l < LLN) ? l : (LLN - 1);
        ebuf[i] = ((const float4*)(eb + (size_t)lc * BB * HH))[lane * 2 + 1];
    }
#pragma unroll
    for (int i = 0; i < 7; i++) {
        float r;
        r = frcp(fmaf(Q1.x, ebuf[i].x, 1.f)); s[i] = fmaf(v1.x, r, s[i]);
        r = frcp(fmaf(Q1.y, ebuf[i].y, 1.f)); s[i] = fmaf(v1.y, r, s[i]);
        r = frcp(fmaf(Q1.z, ebuf[i].z, 1.f)); s[i] = fmaf(v1.z, r, s[i]);
        r = frcp(fmaf(Q1.w, ebuf[i].w, 1.f)); s[i] = fmaf(v1.w, r, s[i]);
    }
#pragma unroll
    for (int o = 16; o; o >>= 1)
#pragma unroll
        for (int i = 0; i < 7; i++) s[i] += __shfl_xor_sync(0xffffffffu, s[i], o);
    if (lane == 0) {
#pragma unroll
        for (int i = 0; i < 7; i++) {
            int l = w + 8 * i;
            if (l < LLN) sp[l] = g_mask[b * LLN + l] ? NEGV : fmaf(-2.f, s[i], sv);
        }
    }
    __syncthreads();
    if (w == 0) {
        float a  = (lane < LLN) ? sp[lane] : -FLT_MAX;
        float bb = (lane + 32 < LLN) ? sp[lane + 32] : -FLT_MAX;
        float m = fmaxf(a, bb);
#pragma unroll
        for (int o = 16; o; o >>= 1) m = fmaxf(m, __shfl_xor_sync(0xffffffffu, m, o));
        float ea  = (lane < LLN) ? __expf(a - m) : 0.f;
        float eb2 = (lane + 32 < LLN) ? __expf(bb - m) : 0.f;
        if (lane < LLN) sp[lane] = ea;
        if (lane + 32 < LLN) sp[lane + 32] = eb2;
        float ssum = ea + eb2;
#pragma unroll
        for (int o = 16; o; o >>= 1) ssum += __shfl_xor_sync(0xffffffffu, ssum, o);
        if (lane == 0) s_inv = __fdividef(1.f, ssum);
    }
    __syncthreads();
    float inv = s_inv;
    // combine: e = 0.5*ln(E); g = 0.5*inv * sum_l sp[l]*ln(E[l])
    const float* ec = eb + tid;
    float a0 = 0.f, a1 = 0.f;
#pragma unroll
    for (int l = 0; l < LLN; l += 2) {
        a0 = fmaf(sp[l],     __logf(ec[(size_t) l      * BB * HH]), a0);
        a1 = fmaf(sp[l + 1], __logf(ec[(size_t)(l + 1) * BB * HH]), a1);
    }
    g_g[(size_t)b * HH + tid] = (a0 + a1) * (0.5f * inv);
}

// ---- pointer attention: exp-form u-pass, log_softmax, argmax, gather ------
__global__ void k_attn_pt(const float* __restrict__ v, const float* __restrict__ emb,
                          float* __restrict__ out, float* __restrict__ sel_out,
                          int t, int wsel, float* __restrict__ xh_next) {
    int b = blockIdx.x, tid = threadIdx.x, lane = tid & 31, w = tid >> 5;
    __shared__ __align__(16) float qs[HH], vs[HH];
    __shared__ float sp[LLN];
    __shared__ float s_lse;
    __shared__ int s_idx;
    qs[tid] = g_qpt0[(size_t)b * HH + tid] + g_qpt1[(size_t)b * HH + tid];
    vs[tid] = v[tid];
    __syncthreads();

    const float* eb = g_e_pt + (size_t)b * HH;
    float4 Q0 = ((const float4*)qs)[lane * 2], Q1 = ((const float4*)qs)[lane * 2 + 1];
    Q0.x = fexp2e(Q0.x); Q0.y = fexp2e(Q0.y); Q0.z = fexp2e(Q0.z); Q0.w = fexp2e(Q0.w);
    Q1.x = fexp2e(Q1.x); Q1.y = fexp2e(Q1.y); Q1.z = fexp2e(Q1.z); Q1.w = fexp2e(Q1.w);
    float4 v0 = ((const float4*)vs)[lane * 2], v1 = ((const float4*)vs)[lane * 2 + 1];
    float sv = ((v0.x + v0.y) + (v0.z + v0.w)) + ((v1.x + v1.y) + (v1.z + v1.w));
#pragma unroll
    for (int o = 16; o; o >>= 1) sv += __shfl_xor_sync(0xffffffffu, sv, o);

    float s[7];
    float4 ebuf[7];
#pragma unroll
    for (int i = 0; i < 7; i++) {
        int l = w + 8 * i; int lc = (l < LLN) ? l : (LLN - 1);
        ebuf[i] = ((const float4*)(eb + (size_t)lc * BB * HH))[lane * 2];
    }
#pragma unroll
    for (int i = 0; i < 7; i++) {
        float r;
        r = frcp(fmaf(Q0.x, ebuf[i].x, 1.f)); s[i] = v0.x * r;
        r = frcp(fmaf(Q0.y, ebuf[i].y, 1.f)); s[i] = fmaf(v0.y, r, s[i]);
        r = frcp(fmaf(Q0.z, ebuf[i].z, 1.f)); s[i] = fmaf(v0.z, r, s[i]);
        r = frcp(fmaf(Q0.w, ebuf[i].w, 1.f)); s[i] = fmaf(v0.w, r, s[i]);
    }
#pragma unroll
    for (int i = 0; i < 7; i++) {
        int l = w + 8 * i; int lc = (l < LLN) ? l : (LLN - 1);
        ebuf[i] = ((const float4*)(eb + (size_t)lc * BB * HH))[lane * 2 + 1];
    }
#pragma unroll
    for (int i = 0; i < 7; i++) {
        float r;
        r = frcp(fmaf(Q1.x, ebuf[i].x, 1.f)); s[i] = fmaf(v1.x, r, s[i]);
        r = frcp(fmaf(Q1.y, ebuf[i].y, 1.f)); s[i] = fmaf(v1.y, r, s[i]);
        r = frcp(fmaf(Q1.z, ebuf[i].z, 1.f)); s[i] = fmaf(v1.z, r, s[i]);
        r = frcp(fmaf(Q1.w, ebuf[i].w, 1.f)); s[i] = fmaf(v1.w, r, s[i]);
    }
#pragma unroll
    for (int o = 16; o; o >>= 1)
#pragma unroll
        for (int i = 0; i < 7; i++) s[i] += __shfl_xor_sync(0xffffffffu, s[i], o);
    if (lane == 0) {
#pragma unroll
        for (int i = 0; i < 7; i++) {
            int l = w + 8 * i;
            if (l < LLN)
                sp[l] = g_mask[b * LLN + l] ? NEGV
                                            : (CEXPL * fast_tanh(fmaf(-2.f, s[i], sv)));
        }
    }
    __syncthreads();
    if (w == 0) {
        float a  = (lane < LLN) ? sp[lane] : -FLT_MAX;           int ia = lane;
        float bb = (lane + 32 < LLN) ? sp[lane + 32] : -FLT_MAX; int ib = lane + 32;
        float m; int mi;
        if (bb > a) { m = bb; mi = ib; } else { m = a; mi = ia; }
#pragma unroll
        for (int o = 16; o; o >>= 1) {
            float om = __shfl_xor_sync(0xffffffffu, m, o);
            int   oi = __shfl_xor_sync(0xffffffffu, mi, o);
            if (om > m || (om == m && oi < mi)) { m = om; mi = oi; }
        }
        float ssum = ((lane < LLN) ? __expf(a - m) : 0.f)
                   + ((lane + 32 < LLN) ? __expf(bb - m) : 0.f);
#pragma unroll
        for (int o = 16; o; o >>= 1) ssum += __shfl_xor_sync(0xffffffffu, ssum, o);
        if (lane == 0) { s_lse = m + __logf(ssum); s_idx = mi; }
    }
    __syncthreads();
    int idx = s_idx; float lse = s_lse;
    if (tid < LLN)
        out[((size_t)b * LLN + t) * LLN + tid] = sp[tid] - lse;
    xh_next[(size_t)b * KK2 + tid] = emb[((size_t)idx * BB + b) * EE + tid];
    if (tid == 0) {
        g_mask[b * LLN + idx] = 1;       // mask for NEXT step
        int cnt = 0;
#pragma unroll
        for (int l = 0; l < LLN; l++) cnt += g_mask[b * LLN + l];
        if (cnt == LLN) g_mask[b * LLN + LLN - 1] = 0;   // ref's all-true reset
        if (wsel) sel_out[b * LLN + t] = (float)idx;
    }
}

// -------------------------------- launch ----------------------------------
extern "C" void kernel_launch(void* const* d_in, const int* in_sizes, int n_in,
                              void* d_out, int out_size) {
    (void)in_sizes; (void)n_in;
    const float* dec  = (const float*)d_in[0];
    const float* emb  = (const float*)d_in[1];
    const float* h0   = (const float*)d_in[2];
    const float* c0   = (const float*)d_in[3];
    const float* ctx  = (const float*)d_in[4];
    const float* Wih  = (const float*)d_in[6];
    const float* Whh  = (const float*)d_in[7];
    const float* bih  = (const float*)d_in[8];
    const float* bhh  = (const float*)d_in[9];
    const float* glWq = (const float*)d_in[10];
    const float* glbq = (const float*)d_in[11];
    const float* glWr = (const float*)d_in[12];
    const float* glbr = (const float*)d_in[13];
    const float* glv  = (const float*)d_in[14];
    const float* ptWq = (const float*)d_in[15];
    const float* ptbq = (const float*)d_in[16];
    const float* ptWr = (const float*)d_in[17];
    const float* ptbr = (const float*)d_in[18];
    const float* ptv  = (const float*)d_in[19];
    float* out = (float*)d_out;

    float *pe_gl, *pe_pt, *pxh0, *pxh1, *pg, *pzero;
    float *pqgl0, *pqgl1, *pqpt0, *pqpt1;
    cudaGetSymbolAddress((void**)&pe_gl, g_e_gl);
    cudaGetSymbolAddress((void**)&pe_pt, g_e_pt);
    cudaGetSymbolAddress((void**)&pxh0,  g_xh0);
    cudaGetSymbolAddress((void**)&pxh1,  g_xh1);
    cudaGetSymbolAddress((void**)&pg,    g_g);
    cudaGetSymbolAddress((void**)&pzero, g_zero);
    cudaGetSymbolAddress((void**)&pqgl0, g_qgl0);
    cudaGetSymbolAddress((void**)&pqgl1, g_qgl1);
    cudaGetSymbolAddress((void**)&pqpt0, g_qpt0);
    cudaGetSymbolAddress((void**)&pqpt1, g_qpt1);

    k_init<<<2048, 256>>>(dec, h0, c0);
    k_prep_lstm<<<H4, 256>>>(Wih, Whh, bih, bhh);

    // Time-invariant projections (z=2): e_gl = ctx@glWr^T+glbr ; e_pt = ctx@ptWr^T+ptbr
    {
        GA a0{ctx, HH, glWr, HH, glbr, pe_gl};
        GA a1{ctx, HH, ptWr, HH, ptbr, pe_pt};
        dim3 g(HH / 128, (LLN * BB) / 128, 2);
        gemm_multi<128, 128, 16, 8, 8><<<g, 256>>>(a0, a1, HH, HH);
    }
    // transform both e buffers in place: e -> exp(2e)
    k_exp<<<dim3((LLN * BB * HH / 4) / 256, 2), 256>>>();

    const size_t BLLL = (size_t)BB * LLN * LLN;
    const int wsel = (out_size >= (int)(BLLL + (size_t)BB * LLN)) ? 1 : 0;

    float* xh[2] = {pxh0, pxh1};
    for (int t = 0; t < LLN; t++) {
        float* cur = xh[t & 1];
        float* nxt = xh[(t + 1) & 1];
        // LSTM gates, split-K x4 -> g_G[0..3]; 1024 CTAs of 128 thr (R7 config)
        k_lstm4<<<dim3(H4 / 64, BB / 64, KSPLIT), 128>>>(cur);
        // cell: sum partials, nonlinearity, h_t -> nxt[:,256:512]
        k_cell<<<BB, HH>>>(nxt);
        // q_gl split-K x2 (bias in z=0; partials summed in k_attn_gl)
        {
            GA a0{nxt + EE,       KK2, glWq,       HH, glbq,  pqgl0};
            GA a1{nxt + EE + 128, KK2, glWq + 128, HH, pzero, pqgl1};
            gemm_multi<32, 64, 16, 4, 4><<<dim3(HH / 64, BB / 32, 2), 128>>>(a0, a1, HH, 128);
        }
        // glimpse attention -> g
        k_attn_gl<<<BB, HH>>>(glv);
        // q_pt split-K x2
        {
            GA a0{pg,       HH, ptWq,       HH, ptbq,  pqpt0};
            GA a1{pg + 128, HH, ptWq + 128, HH, pzero, pqpt1};
            gemm_multi<32, 64, 16, 4, 4><<<dim3(HH / 64, BB / 32, 2), 128>>>(a0, a1, HH, 128);
        }
        // pointer attention: log_p -> out, argmax, gather x_{t+1}, mask update
        k_attn_pt<<<BB, HH>>>(ptv, emb, out, out + BLLL, t, wsel, nxt);
    }
}

// round 15
// speedup vs baseline: 1.1854x; 1.0370x over previous
#include <cuda_runtime.h>
#include <math.h>
#include <float.h>

#define BB 1024
#define LLN 50
#define EE 256
#define HH 256
#define KK2 512          // E + H
#define H4 1024
#define NEGV (-1e9f)
#define CEXPL 10.0f
#define KSPLIT 4
#define KSEG (KK2 / KSPLIT)   // 128

typedef unsigned long long u64;

// ---------------- device scratch (no allocations allowed) ----------------
// After k_exp transform, g_e_gl / g_e_pt hold exp(2*e), not e.
__device__ __align__(16) float g_e_gl[(size_t)LLN * BB * HH];  // 52.4 MB
__device__ __align__(16) float g_e_pt[(size_t)LLN * BB * HH];  // 52.4 MB
__device__ __align__(16) float g_xh0[BB * KK2];                // [x | h] ping
__device__ __align__(16) float g_xh1[BB * KK2];                // [x | h] pong
__device__ __align__(16) float g_c  [BB * HH];
__device__ __align__(16) float g_qgl0[BB * HH];
__device__ __align__(16) float g_qgl1[BB * HH];
__device__ __align__(16) float g_g   [BB * HH];
__device__ __align__(16) float g_qpt0[BB * HH];
__device__ __align__(16) float g_qpt1[BB * HH];
__device__ __align__(16) float g_G  [(size_t)KSPLIT * BB * H4]; // split-K partials
__device__ __align__(16) float g_Wc [H4 * KK2];                // gate-interleaved [Wih|Whh]
__device__ __align__(16) float g_bc [H4];
__device__ __align__(16) float g_zero[H4];                     // static zero bias
__device__ unsigned char g_mask[BB * LLN];

// ---------------- PDL intrinsics (sm_90+) ---------------------------------
// launch_dependents MUST be executed only after all stores that dependents read.
__device__ __forceinline__ void gdep_wait()   { asm volatile("griddepcontrol.wait;" ::: "memory"); }
__device__ __forceinline__ void gdep_launch() { asm volatile("griddepcontrol.launch_dependents;" ::: "memory"); }

// ---------------- packed fp32x2 helpers (IEEE-exact per lane) -------------
__device__ __forceinline__ u64 pk2(float x, float y) {
    u64 r; asm("mov.b64 %0,{%1,%2};" : "=l"(r) : "f"(x), "f"(y)); return r;
}
__device__ __forceinline__ u64 pkdup(float x) {
    u64 r; asm("mov.b64 %0,{%1,%1};" : "=l"(r) : "f"(x)); return r;
}
__device__ __forceinline__ u64 ffma2(u64 a, u64 b, u64 c) {
    u64 d; asm("fma.rn.f32x2 %0,%1,%2,%3;" : "=l"(d) : "l"(a), "l"(b), "l"(c)); return d;
}
__device__ __forceinline__ float2 upk(u64 a) {
    float2 f; asm("mov.b64 {%0,%1},%2;" : "=f"(f.x), "=f"(f.y) : "l"(a)); return f;
}
__device__ __forceinline__ float frcp(float x) {
    float r; asm("rcp.approx.f32 %0,%1;" : "=f"(r) : "f"(x)); return r;
}

// ---------------- FMA-pipe exp2 (deg-7 Horner, rel err ~1e-8) -------------
__device__ __forceinline__ float fexp2(float y) {
    float k = y + 12582912.0f;              // RN round-to-int via magic
    float f = y - (k - 12582912.0f);        // f in [-0.5, 0.5], exact
    float p =            1.5252734e-5f;
    p = fmaf(p, f, 1.5403530e-4f);
    p = fmaf(p, f, 1.3333558e-3f);
    p = fmaf(p, f, 9.6181291e-3f);
    p = fmaf(p, f, 5.5504109e-2f);
    p = fmaf(p, f, 2.4022651e-1f);
    p = fmaf(p, f, 6.9314718e-1f);
    p = fmaf(p, f, 1.0f);
    float sc = __int_as_float((__float_as_int(k) - 1262485377) << 23);
    return p * sc;
}

// exp(2x), clamped to finite fp32 range
__device__ __forceinline__ float fexp2e(float x) {
    float y = fminf(fmaxf(x * 2.8853901f, -126.0f), 126.0f);  // 2*log2(e)*x
    return fexp2(y);
}

// scalar tanh (cell + pointer logits); rel err ~1e-7
__device__ __forceinline__ float fast_tanh(float x) {
    float ax = fabsf(x);
    float y  = fminf(ax * 2.8853901f, 126.0f);
    float e2 = fexp2(y);
    float r  = 1.0f - __fdividef(2.0f, e2 + 1.0f);
    return copysignf(r, x);
}
__device__ __forceinline__ float sigm(float x) {
    float y = fminf(fmaxf(-x * 1.4426950f, -126.0f), 126.0f);
    return __fdividef(1.0f, 1.0f + fexp2(y));
}

// ---------------- init ---------------------------------------------------
__global__ void k_init(const float* __restrict__ dec, const float* __restrict__ h0,
                       const float* __restrict__ c0) {
    int i = blockIdx.x * blockDim.x + threadIdx.x;
    if (i < BB * KK2) {
        int b = i >> 9, k = i & 511;
        g_xh0[i] = (k < EE) ? dec[b * EE + k] : h0[b * HH + (k - EE)];
    }
    if (i < BB * HH)  g_c[i] = c0[i];
    if (i < BB * LLN) g_mask[i] = 0;
}

// ---------------- weight prep (one-time) ----------------------------------
__global__ void k_prep_lstm(const float* __restrict__ Wih, const float* __restrict__ Whh,
                            const float* __restrict__ bih, const float* __restrict__ bhh) {
    int r = blockIdx.x;
    int j = r >> 2, g = r & 3;
    int src = g * HH + j;
    for (int k = threadIdx.x; k < EE; k += blockDim.x)
        g_Wc[(size_t)r * KK2 + k] = Wih[(size_t)src * EE + k];
    for (int k = threadIdx.x; k < HH; k += blockDim.x)
        g_Wc[(size_t)r * KK2 + EE + k] = Whh[(size_t)src * HH + k];
    if (threadIdx.x == 0) g_bc[r] = bih[src] + bhh[src];
}

// ---------------- in-place transform: e -> exp(2e) -------------------------
__global__ void k_exp() {
    gdep_wait();                         // e buffers from immediate pred (big gemm)
    size_t i = (size_t)blockIdx.x * blockDim.x + threadIdx.x;   // float4 index
    float4* p = (blockIdx.y == 0) ? (float4*)g_e_gl : (float4*)g_e_pt;
    float4 v = p[i];
    v.x = fexp2e(v.x); v.y = fexp2e(v.y); v.z = fexp2e(v.z); v.w = fexp2e(v.w);
    p[i] = v;
    gdep_launch();                       // after E stores
}

// ---------------- generic NT GEMM with G->reg prefetch + PDL ---------------
struct GA { const float* A; int lda; const float* W; int wlda;
            const float* bias; float* C; };

template <int BM, int BN, int BK, int TM, int TN>
__global__ void gemm_multi(GA a0, GA a1, int N, int K) {
    constexpr int THREADS = (BM / TM) * (BN / TN);
    constexpr int A_LDS = BM * BK / THREADS / 4;
    constexpr int W_LDS = BN * BK / THREADS / 4;

    GA g = (blockIdx.z == 0) ? a0 : a1;

    __shared__ __align__(16) float As[BK][BM];
    __shared__ __align__(16) float Ws[BK][BN];

    const int tid = threadIdx.x;
    const int tx  = tid % (BN / TN);
    const int ty  = tid / (BN / TN);
    const int m0  = blockIdx.y * BM;
    const int n0  = blockIdx.x * BN;

    u64 acc[TM][TN / 2];
#pragma unroll
    for (int i = 0; i < TM; i++)
#pragma unroll
        for (int j = 0; j < TN / 2; j++) acc[i][j] = pk2(0.f, 0.f);

    float4 pa[A_LDS], pw[W_LDS];
    // W is a constant input weight -> safe before the grid-dependency wait
#pragma unroll
    for (int i = 0; i < W_LDS; i++) {
        int li = tid + i * THREADS;
        pw[i] = *(const float4*)(g.W + (size_t)(n0 + li / (BK / 4)) * g.wlda + (li % (BK / 4)) * 4);
    }
    gdep_wait();                          // A may be written by immediate predecessor
#pragma unroll
    for (int i = 0; i < A_LDS; i++) {
        int li = tid + i * THREADS;
        pa[i] = *(const float4*)(g.A + (size_t)(m0 + li / (BK / 4)) * g.lda + (li % (BK / 4)) * 4);
    }

    for (int k0 = 0; k0 < K; k0 += BK) {
#pragma unroll
        for (int i = 0; i < A_LDS; i++) {
            int li = tid + i * THREADS;
            int r = li / (BK / 4), c4 = li % (BK / 4);
            As[c4 * 4 + 0][r] = pa[i].x; As[c4 * 4 + 1][r] = pa[i].y;
            As[c4 * 4 + 2][r] = pa[i].z; As[c4 * 4 + 3][r] = pa[i].w;
        }
#pragma unroll
        for (int i = 0; i < W_LDS; i++) {
            int li = tid + i * THREADS;
            int r = li / (BK / 4), c4 = li % (BK / 4);
            Ws[c4 * 4 + 0][r] = pw[i].x; Ws[c4 * 4 + 1][r] = pw[i].y;
            Ws[c4 * 4 + 2][r] = pw[i].z; Ws[c4 * 4 + 3][r] = pw[i].w;
        }
        __syncthreads();

        if (k0 + BK < K) {
#pragma unroll
            for (int i = 0; i < A_LDS; i++) {
                int li = tid + i * THREADS;
                pa[i] = *(const float4*)(g.A + (size_t)(m0 + li / (BK / 4)) * g.lda
                                         + k0 + BK + (li % (BK / 4)) * 4);
            }
#pragma unroll
            for (int i = 0; i < W_LDS; i++) {
                int li = tid + i * THREADS;
                pw[i] = *(const float4*)(g.W + (size_t)(n0 + li / (BK / 4)) * g.wlda
                                         + k0 + BK + (li % (BK / 4)) * 4);
            }
        }

#pragma unroll
        for (int kk = 0; kk < BK; kk++) {
            u64 bp[TN / 2];
#pragma unroll
            for (int j = 0; j < TN / 4; j++) {
                float4 wv = *(const float4*)&Ws[kk][tx * TN + j * 4];
                bp[2 * j]     = pk2(wv.x, wv.y);
                bp[2 * j + 1] = pk2(wv.z, wv.w);
            }
#pragma unroll
            for (int i = 0; i < TM; i += 4) {
                float4 av = *(const float4*)&As[kk][ty * TM + i];
                u64 q0 = pkdup(av.x), q1 = pkdup(av.y), q2 = pkdup(av.z), q3 = pkdup(av.w);
#pragma unroll
                for (int j = 0; j < TN / 2; j++) {
                    acc[i + 0][j] = ffma2(q0, bp[j], acc[i + 0][j]);
                    acc[i + 1][j] = ffma2(q1, bp[j], acc[i + 1][j]);
                    acc[i + 2][j] = ffma2(q2, bp[j], acc[i + 2][j]);
                    acc[i + 3][j] = ffma2(q3, bp[j], acc[i + 3][j]);
                }
            }
        }
        __syncthreads();
    }

    const int n = n0 + tx * TN;
    float bb[TN];
#pragma unroll
    for (int j = 0; j < TN; j++) bb[j] = g.bias[n + j];
#pragma unroll
    for (int i = 0; i < TM; i++) {
        int m = m0 + ty * TM + i;
#pragma unroll
        for (int j = 0; j < TN / 4; j++) {
            float2 u0 = upk(acc[i][2 * j]);
            float2 u1 = upk(acc[i][2 * j + 1]);
            float4 r;
            r.x = u0.x + bb[4 * j];     r.y = u0.y + bb[4 * j + 1];
            r.z = u1.x + bb[4 * j + 2]; r.w = u1.y + bb[4 * j + 3];
            *(float4*)(g.C + (size_t)m * N + n + 4 * j) = r;
        }
    }
    gdep_launch();                        // after C stores
}

// ---------------- LSTM gates, split-K x4 (R7-proven config) + PDL ----------
__global__ void k_lstm4(const float* __restrict__ A0) {
    constexpr int BM = 64, BN = 64, BK = 16, TM = 8;
    constexpr int THREADS = 128;

    __shared__ __align__(16) float As[BK][BM];
    __shared__ __align__(16) float Ws[BK][BN];

    const int tid = threadIdx.x;
    const int tx  = tid % 16;           // BN/TN
    const int ty  = tid / 16;
    const int m0  = blockIdx.y * BM;
    const int n0  = blockIdx.x * BN;
    const int z   = blockIdx.z;

    const float* A = A0 + z * KSEG;          // row stride KK2
    const float* W = g_Wc + z * KSEG;        // row stride KK2
    float* C = g_G + (size_t)z * BB * H4;

    u64 acc[TM][2];
#pragma unroll
    for (int i = 0; i < TM; i++) { acc[i][0] = pk2(0.f, 0.f); acc[i][1] = pk2(0.f, 0.f); }

    float4 pa[2], pw[2];
    // W (g_Wc) is many kernels old -> safe before wait
#pragma unroll
    for (int i = 0; i < 2; i++) {
        int li = tid + i * THREADS;
        pw[i] = *(const float4*)(W + (size_t)(n0 + li / 4) * KK2 + (li % 4) * 4);
    }
    gdep_wait();                          // xh written by immediate pred chain
#pragma unroll
    for (int i = 0; i < 2; i++) {
        int li = tid + i * THREADS;
        pa[i] = *(const float4*)(A + (size_t)(m0 + li / 4) * KK2 + (li % 4) * 4);
    }

    for (int k0 = 0; k0 < KSEG; k0 += BK) {
#pragma unroll
        for (int i = 0; i < 2; i++) {
            int li = tid + i * THREADS;
            int r = li / 4, c4 = li % 4;
            As[c4 * 4 + 0][r] = pa[i].x; As[c4 * 4 + 1][r] = pa[i].y;
            As[c4 * 4 + 2][r] = pa[i].z; As[c4 * 4 + 3][r] = pa[i].w;
            Ws[c4 * 4 + 0][r] = pw[i].x; Ws[c4 * 4 + 1][r] = pw[i].y;
            Ws[c4 * 4 + 2][r] = pw[i].z; Ws[c4 * 4 + 3][r] = pw[i].w;
        }
        __syncthreads();

        if (k0 + BK < KSEG) {
#pragma unroll
            for (int i = 0; i < 2; i++) {
                int li = tid + i * THREADS;
                pa[i] = *(const float4*)(A + (size_t)(m0 + li / 4) * KK2
                                         + k0 + BK + (li % 4) * 4);
                pw[i] = *(const float4*)(W + (size_t)(n0 + li / 4) * KK2
                                         + k0 + BK + (li % 4) * 4);
            }
        }

#pragma unroll
        for (int kk = 0; kk < BK; kk++) {
            float4 bv = *(const float4*)&Ws[kk][tx * 4];
            u64 bp0 = pk2(bv.x, bv.y);
            u64 bp1 = pk2(bv.z, bv.w);
#pragma unroll
            for (int i = 0; i < TM; i += 4) {
                float4 av = *(const float4*)&As[kk][ty * TM + i];
                u64 q0 = pkdup(av.x), q1 = pkdup(av.y), q2 = pkdup(av.z), q3 = pkdup(av.w);
                acc[i + 0][0] = ffma2(q0, bp0, acc[i + 0][0]);
                acc[i + 0][1] = ffma2(q0, bp1, acc[i + 0][1]);
                acc[i + 1][0] = ffma2(q1, bp0, acc[i + 1][0]);
                acc[i + 1][1] = ffma2(q1, bp1, acc[i + 1][1]);
                acc[i + 2][0] = ffma2(q2, bp0, acc[i + 2][0]);
                acc[i + 2][1] = ffma2(q2, bp1, acc[i + 2][1]);
                acc[i + 3][0] = ffma2(q3, bp0, acc[i + 3][0]);
                acc[i + 3][1] = ffma2(q3, bp1, acc[i + 3][1]);
            }
        }
        __syncthreads();
    }

    const int n = n0 + tx * 4;
#pragma unroll
    for (int i = 0; i < TM; i++) {
        int m = m0 + ty * TM + i;
        float2 u0 = upk(acc[i][0]);
        float2 u1 = upk(acc[i][1]);
        float4 r; r.x = u0.x; r.y = u0.y; r.z = u1.x; r.w = u1.y;
        *(float4*)(C + (size_t)m * H4 + n) = r;
    }
    gdep_launch();                        // after partial stores
}

// ---------------- LSTM cell: sum 4 split-K partials + nonlinearity ---------
__global__ void k_cell(float* __restrict__ xh_next) {
    gdep_wait();                          // g_G from immediate pred
    int b = blockIdx.x, j = threadIdx.x;  // 1024 x 256
    size_t off = (size_t)b * H4 + 4 * j;
    const float4 p0 = *(const float4*)(g_G + off);
    const float4 p1 = *(const float4*)(g_G + (size_t)1 * BB * H4 + off);
    const float4 p2 = *(const float4*)(g_G + (size_t)2 * BB * H4 + off);
    const float4 p3 = *(const float4*)(g_G + (size_t)3 * BB * H4 + off);
    const float4 bc = *(const float4*)(g_bc + 4 * j);
    float gi = (p0.x + p1.x) + (p2.x + p3.x) + bc.x;
    float gf = (p0.y + p1.y) + (p2.y + p3.y) + bc.y;
    float gg = (p0.z + p1.z) + (p2.z + p3.z) + bc.z;
    float go = (p0.w + p1.w) + (p2.w + p3.w) + bc.w;
    float c  = g_c[(size_t)b * HH + j];
    float c2 = sigm(gf) * c + sigm(gi) * fast_tanh(gg);
    g_c[(size_t)b * HH + j] = c2;
    xh_next[(size_t)b * KK2 + EE + j] = sigm(go) * fast_tanh(c2);
    gdep_launch();                        // after h/c stores
}

// ------ glimpse attention: exp-form u-pass, softmax, log-combine -> g ------
__global__ void k_attn_gl(const float* __restrict__ v) {
    int b = blockIdx.x, tid = threadIdx.x, lane = tid & 31, w = tid >> 5;
    __shared__ __align__(16) float qs[HH], vs[HH];
    __shared__ float sp[LLN];
    __shared__ float s_inv;
    vs[tid] = v[tid];                     // const input: safe pre-wait
    gdep_wait();                          // q from immediate pred (q_gl gemm)
    qs[tid] = g_qgl0[(size_t)b * HH + tid] + g_qgl1[(size_t)b * HH + tid];
    __syncthreads();

    const float* eb = g_e_gl + (size_t)b * HH;
    float4 Q0 = ((const float4*)qs)[lane * 2], Q1 = ((const float4*)qs)[lane * 2 + 1];
    Q0.x = fexp2e(Q0.x); Q0.y = fexp2e(Q0.y); Q0.z = fexp2e(Q0.z); Q0.w = fexp2e(Q0.w);
    Q1.x = fexp2e(Q1.x); Q1.y = fexp2e(Q1.y); Q1.z = fexp2e(Q1.z); Q1.w = fexp2e(Q1.w);
    float4 v0 = ((const float4*)vs)[lane * 2], v1 = ((const float4*)vs)[lane * 2 + 1];
    float sv = ((v0.x + v0.y) + (v0.z + v0.w)) + ((v1.x + v1.y) + (v1.z + v1.w));
#pragma unroll
    for (int o = 16; o; o >>= 1) sv += __shfl_xor_sync(0xffffffffu, sv, o);

    float s[7];
    float4 ebuf[7];
#pragma unroll
    for (int i = 0; i < 7; i++) {                 // batch 7 independent L2 loads
        int l = w + 8 * i; int lc = (l < LLN) ? l : (LLN - 1);
        ebuf[i] = ((const float4*)(eb + (size_t)lc * BB * HH))[lane * 2];
    }
#pragma unroll
    for (int i = 0; i < 7; i++) {
        float r;
        r = frcp(fmaf(Q0.x, ebuf[i].x, 1.f)); s[i] = v0.x * r;
        r = frcp(fmaf(Q0.y, ebuf[i].y, 1.f)); s[i] = fmaf(v0.y, r, s[i]);
        r = frcp(fmaf(Q0.z, ebuf[i].z, 1.f)); s[i] = fmaf(v0.z, r, s[i]);
        r = frcp(fmaf(Q0.w, ebuf[i].w, 1.f)); s[i] = fmaf(v0.w, r, s[i]);
    }
#pragma unroll
    for (int i = 0; i < 7; i++) {
        int l = w + 8 * i; int lc = (l < LLN) ? l : (LLN - 1);
        ebuf[i] = ((const float4*)(eb + (size_t)lc * BB * HH))[lane * 2 + 1];
    }
#pragma unroll
    for (int i = 0; i < 7; i++) {
        float r;
        r = frcp(fmaf(Q1.x, ebuf[i].x, 1.f)); s[i] = fmaf(v1.x, r, s[i]);
        r = frcp(fmaf(Q1.y, ebuf[i].y, 1.f)); s[i] = fmaf(v1.y, r, s[i]);
        r = frcp(fmaf(Q1.z, ebuf[i].z, 1.f)); s[i] = fmaf(v1.z, r, s[i]);
        r = frcp(fmaf(Q1.w, ebuf[i].w, 1.f)); s[i] = fmaf(v1.w, r, s[i]);
    }
#pragma unroll
    for (int o = 16; o; o >>= 1)
#pragma unroll
        for (int i = 0; i < 7; i++) s[i] += __shfl_xor_sync(0xffffffffu, s[i], o);
    if (lane == 0) {
#pragma unroll
        for (int i = 0; i < 7; i++) {
            int l = w + 8 * i;
            if (l < LLN) sp[l] = g_mask[b * LLN + l] ? NEGV : fmaf(-2.f, s[i], sv);
        }
    }
    __syncthreads();
    if (w == 0) {
        float a  = (lane < LLN) ? sp[lane] : -FLT_MAX;
        float bb = (lane + 32 < LLN) ? sp[lane + 32] : -FLT_MAX;
        float m = fmaxf(a, bb);
#pragma unroll
        for (int o = 16; o; o >>= 1) m = fmaxf(m, __shfl_xor_sync(0xffffffffu, m, o));
        float ea  = (lane < LLN) ? __expf(a - m) : 0.f;
        float eb2 = (lane + 32 < LLN) ? __expf(bb - m) : 0.f;
        if (lane < LLN) sp[lane] = ea;
        if (lane + 32 < LLN) sp[lane + 32] = eb2;
        float ssum = ea + eb2;
#pragma unroll
        for (int o = 16; o; o >>= 1) ssum += __shfl_xor_sync(0xffffffffu, ssum, o);
        if (lane == 0) s_inv = __fdividef(1.f, ssum);
    }
    __syncthreads();
    float inv = s_inv;
    // combine: e = 0.5*ln(E); g = 0.5*inv * sum_l sp[l]*ln(E[l])
    const float* ec = eb + tid;
    float a0 = 0.f, a1 = 0.f;
#pragma unroll
    for (int l = 0; l < LLN; l += 2) {
        a0 = fmaf(sp[l],     __logf(ec[(size_t) l      * BB * HH]), a0);
        a1 = fmaf(sp[l + 1], __logf(ec[(size_t)(l + 1) * BB * HH]), a1);
    }
    g_g[(size_t)b * HH + tid] = (a0 + a1) * (0.5f * inv);
    gdep_launch();                        // after g stores
}

// ---- pointer attention: exp-form u-pass, log_softmax, argmax, gather ------
__global__ void k_attn_pt(const float* __restrict__ v, const float* __restrict__ emb,
                          float* __restrict__ out, float* __restrict__ sel_out,
                          int t, int wsel, float* __restrict__ xh_next) {
    int b = blockIdx.x, tid = threadIdx.x, lane = tid & 31, w = tid >> 5;
    __shared__ __align__(16) float qs[HH], vs[HH];
    __shared__ float sp[LLN];
    __shared__ float s_lse;
    __shared__ int s_idx;
    vs[tid] = v[tid];                     // const input: safe pre-wait
    gdep_wait();                          // q from immediate pred (q_pt gemm)
    qs[tid] = g_qpt0[(size_t)b * HH + tid] + g_qpt1[(size_t)b * HH + tid];
    __syncthreads();

    const float* eb = g_e_pt + (size_t)b * HH;
    float4 Q0 = ((const float4*)qs)[lane * 2], Q1 = ((const float4*)qs)[lane * 2 + 1];
    Q0.x = fexp2e(Q0.x); Q0.y = fexp2e(Q0.y); Q0.z = fexp2e(Q0.z); Q0.w = fexp2e(Q0.w);
    Q1.x = fexp2e(Q1.x); Q1.y = fexp2e(Q1.y); Q1.z = fexp2e(Q1.z); Q1.w = fexp2e(Q1.w);
    float4 v0 = ((const float4*)vs)[lane * 2], v1 = ((const float4*)vs)[lane * 2 + 1];
    float sv = ((v0.x + v0.y) + (v0.z + v0.w)) + ((v1.x + v1.y) + (v1.z + v1.w));
#pragma unroll
    for (int o = 16; o; o >>= 1) sv += __shfl_xor_sync(0xffffffffu, sv, o);

    float s[7];
    float4 ebuf[7];
#pragma unroll
    for (int i = 0; i < 7; i++) {
        int l = w + 8 * i; int lc = (l < LLN) ? l : (LLN - 1);
        ebuf[i] = ((const float4*)(eb + (size_t)lc * BB * HH))[lane * 2];
    }
#pragma unroll
    for (int i = 0; i < 7; i++) {
        float r;
        r = frcp(fmaf(Q0.x, ebuf[i].x, 1.f)); s[i] = v0.x * r;
        r = frcp(fmaf(Q0.y, ebuf[i].y, 1.f)); s[i] = fmaf(v0.y, r, s[i]);
        r = frcp(fmaf(Q0.z, ebuf[i].z, 1.f)); s[i] = fmaf(v0.z, r, s[i]);
        r = frcp(fmaf(Q0.w, ebuf[i].w, 1.f)); s[i] = fmaf(v0.w, r, s[i]);
    }
#pragma unroll
    for (int i = 0; i < 7; i++) {
        int l = w + 8 * i; int lc = (l < LLN) ? l : (LLN - 1);
        ebuf[i] = ((const float4*)(eb + (size_t)lc * BB * HH))[lane * 2 + 1];
    }
#pragma unroll
    for (int i = 0; i < 7; i++) {
        float r;
        r = frcp(fmaf(Q1.x, ebuf[i].x, 1.f)); s[i] = fmaf(v1.x, r, s[i]);
        r = frcp(fmaf(Q1.y, ebuf[i].y, 1.f)); s[i] = fmaf(v1.y, r, s[i]);
        r = frcp(fmaf(Q1.z, ebuf[i].z, 1.f)); s[i] = fmaf(v1.z, r, s[i]);
        r = frcp(fmaf(Q1.w, ebuf[i].w, 1.f)); s[i] = fmaf(v1.w, r, s[i]);
    }
#pragma unroll
    for (int o = 16; o; o >>= 1)
#pragma unroll
        for (int i = 0; i < 7; i++) s[i] += __shfl_xor_sync(0xffffffffu, s[i], o);
    if (lane == 0) {
#pragma unroll
        for (int i = 0; i < 7; i++) {
            int l = w + 8 * i;
            if (l < LLN)
                sp[l] = g_mask[b * LLN + l] ? NEGV
                                            : (CEXPL * fast_tanh(fmaf(-2.f, s[i], sv)));
        }
    }
    __syncthreads();
    if (w == 0) {
        float a  = (lane < LLN) ? sp[lane] : -FLT_MAX;           int ia = lane;
        float bb = (lane + 32 < LLN) ? sp[lane + 32] : -FLT_MAX; int ib = lane + 32;
        float m; int mi;
        if (bb > a) { m = bb; mi = ib; } else { m = a; mi = ia; }
#pragma unroll
        for (int o = 16; o; o >>= 1) {
            float om = __shfl_xor_sync(0xffffffffu, m, o);
            int   oi = __shfl_xor_sync(0xffffffffu, mi, o);
            if (om > m || (om == m && oi < mi)) { m = om; mi = oi; }
        }
        float ssum = ((lane < LLN) ? __expf(a - m) : 0.f)
                   + ((lane + 32 < LLN) ? __expf(bb - m) : 0.f);
#pragma unroll
        for (int o = 16; o; o >>= 1) ssum += __shfl_xor_sync(0xffffffffu, ssum, o);
        if (lane == 0) { s_lse = m + __logf(ssum); s_idx = mi; }
    }
    __syncthreads();
    int idx = s_idx; float lse = s_lse;
    if (tid < LLN)
        out[((size_t)b * LLN + t) * LLN + tid] = sp[tid] - lse;
    xh_next[(size_t)b * KK2 + tid] = emb[((size_t)idx * BB + b) * EE + tid];
    if (tid == 0) {
        g_mask[b * LLN + idx] = 1;       // mask for NEXT step
        int cnt = 0;
#pragma unroll
        for (int l = 0; l < LLN; l++) cnt += g_mask[b * LLN + l];
        if (cnt == LLN) g_mask[b * LLN + LLN - 1] = 0;   // ref's all-true reset
        if (wsel) sel_out[b * LLN + t] = (float)idx;
    }
    gdep_launch();                        // after all stores (x, mask, out)
}

// -------------------------------- launch ----------------------------------
extern "C" void kernel_launch(void* const* d_in, const int* in_sizes, int n_in,
                              void* d_out, int out_size) {
    (void)in_sizes; (void)n_in;
    const float* dec  = (const float*)d_in[0];
    const float* emb  = (const float*)d_in[1];
    const float* h0   = (const float*)d_in[2];
    const float* c0   = (const float*)d_in[3];
    const float* ctx  = (const float*)d_in[4];
    const float* Wih  = (const float*)d_in[6];
    const float* Whh  = (const float*)d_in[7];
    const float* bih  = (const float*)d_in[8];
    const float* bhh  = (const float*)d_in[9];
    const float* glWq = (const float*)d_in[10];
    const float* glbq = (const float*)d_in[11];
    const float* glWr = (const float*)d_in[12];
    const float* glbr = (const float*)d_in[13];
    const float* glv  = (const float*)d_in[14];
    const float* ptWq = (const float*)d_in[15];
    const float* ptbq = (const float*)d_in[16];
    const float* ptWr = (const float*)d_in[17];
    const float* ptbr = (const float*)d_in[18];
    const float* ptv  = (const float*)d_in[19];
    float* out = (float*)d_out;

    float *pe_gl, *pe_pt, *pxh0, *pxh1, *pg, *pzero;
    float *pqgl0, *pqgl1, *pqpt0, *pqpt1;
    cudaGetSymbolAddress((void**)&pe_gl, g_e_gl);
    cudaGetSymbolAddress((void**)&pe_pt, g_e_pt);
    cudaGetSymbolAddress((void**)&pxh0,  g_xh0);
    cudaGetSymbolAddress((void**)&pxh1,  g_xh1);
    cudaGetSymbolAddress((void**)&pg,    g_g);
    cudaGetSymbolAddress((void**)&pzero, g_zero);
    cudaGetSymbolAddress((void**)&pqgl0, g_qgl0);
    cudaGetSymbolAddress((void**)&pqgl1, g_qgl1);
    cudaGetSymbolAddress((void**)&pqpt0, g_qpt0);
    cudaGetSymbolAddress((void**)&pqpt1, g_qpt1);

    // PDL launch config (programmatic stream serialization)
    cudaLaunchAttribute pdlAttr{};
    pdlAttr.id = cudaLaunchAttributeProgrammaticStreamSerialization;
    pdlAttr.val.programmaticStreamSerializationAllowed = 1;
    auto mkcfg = [&](dim3 g, dim3 b) {
        cudaLaunchConfig_t c{};
        c.gridDim = g; c.blockDim = b; c.dynamicSmemBytes = 0;
        c.stream = 0; c.attrs = &pdlAttr; c.numAttrs = 1;
        return c;
    };

    k_init<<<2048, 256>>>(dec, h0, c0);
    k_prep_lstm<<<H4, 256>>>(Wih, Whh, bih, bhh);

    // Time-invariant projections (z=2): e_gl = ctx@glWr^T+glbr ; e_pt = ctx@ptWr^T+ptbr
    {
        GA a0{ctx, HH, glWr, HH, glbr, pe_gl};
        GA a1{ctx, HH, ptWr, HH, ptbr, pe_pt};
        cudaLaunchConfig_t c = mkcfg(dim3(HH / 128, (LLN * BB) / 128, 2), dim3(256));
        cudaLaunchKernelEx(&c, gemm_multi<128, 128, 16, 8, 8>, a0, a1, (int)HH, (int)KK2 / 2);
    }
    // transform both e buffers in place: e -> exp(2e)
    {
        cudaLaunchConfig_t c = mkcfg(dim3((LLN * BB * HH / 4) / 256, 2), dim3(256));
        cudaLaunchKernelEx(&c, k_exp);
    }

    const size_t BLLL = (size_t)BB * LLN * LLN;
    const int wsel = (out_size >= (int)(BLLL + (size_t)BB * LLN)) ? 1 : 0;

    float* xh[2] = {pxh0, pxh1};
    for (int t = 0; t < LLN; t++) {
        float* cur = xh[t & 1];
        float* nxt = xh[(t + 1) & 1];
        // LSTM gates, split-K x4 -> g_G[0..3]; 1024 CTAs of 128 thr (R7 config)
        {
            cudaLaunchConfig_t c = mkcfg(dim3(H4 / 64, BB / 64, KSPLIT), dim3(128));
            cudaLaunchKernelEx(&c, k_lstm4, (const float*)cur);
        }
        // cell: sum partials, nonlinearity, h_t -> nxt[:,256:512]
        {
            cudaLaunchConfig_t c = mkcfg(dim3(BB), dim3(HH));
            cudaLaunchKernelEx(&c, k_cell, nxt);
        }
        // q_gl split-K x2 (bias in z=0; partials summed in k_attn_gl)
        {
            GA a0{nxt + EE,       KK2, glWq,       HH, glbq,  pqgl0};
            GA a1{nxt + EE + 128, KK2, glWq + 128, HH, pzero, pqgl1};
            cudaLaunchConfig_t c = mkcfg(dim3(HH / 64, BB / 32, 2), dim3(128));
            cudaLaunchKernelEx(&c, gemm_multi<32, 64, 16, 4, 4>, a0, a1, (int)HH, 128);
        }
        // glimpse attention -> g
        {
            cudaLaunchConfig_t c = mkcfg(dim3(BB), dim3(HH));
            cudaLaunchKernelEx(&c, k_attn_gl, glv);
        }
        // q_pt split-K x2
        {
            GA a0{pg,       HH, ptWq,       HH, ptbq,  pqpt0};
            GA a1{pg + 128, HH, ptWq + 128, HH, pzero, pqpt1};
            cudaLaunchConfig_t c = mkcfg(dim3(HH / 64, BB / 32, 2), dim3(128));
            cudaLaunchKernelEx(&c, gemm_multi<32, 64, 16, 4, 4>, a0, a1, (int)HH, 128);
        }
        // pointer attention: log_p -> out, argmax, gather x_{t+1}, mask update
        {
            cudaLaunchConfig_t c = mkcfg(dim3(BB), dim3(HH));
            cudaLaunchKernelEx(&c, k_attn_pt, ptv, emb, out, out + BLLL, t, wsel, nxt);
        }
    }
}

// round 16
// speedup vs baseline: 1.2021x; 1.0141x over previous
#include <cuda_runtime.h>
#include <math.h>
#include <float.h>

#define BB 1024
#define LLN 50
#define EE 256
#define HH 256
#define KK2 512          // E + H
#define H4 1024
#define NEGV (-1e9f)
#define CEXPL 10.0f
#define KSPLIT 4
#define KSEG (KK2 / KSPLIT)   // 128

typedef unsigned long long u64;

// ---------------- device scratch (no allocations allowed) ----------------
// g_e_gl / g_e_pt hold exp(2*e) (written directly by the precompute epilogue).
__device__ __align__(16) float g_e_gl[(size_t)LLN * BB * HH];  // 52.4 MB
__device__ __align__(16) float g_e_pt[(size_t)LLN * BB * HH];  // 52.4 MB
__device__ __align__(16) float g_xh0[BB * KK2];                // [x | h] ping
__device__ __align__(16) float g_xh1[BB * KK2];                // [x | h] pong
__device__ __align__(16) float g_c  [BB * HH];
__device__ __align__(16) float g_qgl0[BB * HH];
__device__ __align__(16) float g_qgl1[BB * HH];
__device__ __align__(16) float g_g   [BB * HH];
__device__ __align__(16) float g_qpt0[BB * HH];
__device__ __align__(16) float g_qpt1[BB * HH];
__device__ __align__(16) float g_G  [(size_t)KSPLIT * BB * H4]; // split-K partials
__device__ __align__(16) float g_Wc [H4 * KK2];                // gate-interleaved [Wih|Whh]
__device__ __align__(16) float g_bc [H4];
__device__ __align__(16) float g_zero[H4];                     // static zero bias
__device__ unsigned char g_mask[BB * LLN];

// ---------------- PDL intrinsics (sm_90+) ---------------------------------
// launch_dependents MUST execute only after all stores that dependents read.
__device__ __forceinline__ void gdep_wait()   { asm volatile("griddepcontrol.wait;" ::: "memory"); }
__device__ __forceinline__ void gdep_launch() { asm volatile("griddepcontrol.launch_dependents;" ::: "memory"); }

// ---------------- packed fp32x2 helpers (IEEE-exact per lane) -------------
__device__ __forceinline__ u64 pk2(float x, float y) {
    u64 r; asm("mov.b64 %0,{%1,%2};" : "=l"(r) : "f"(x), "f"(y)); return r;
}
__device__ __forceinline__ u64 pkdup(float x) {
    u64 r; asm("mov.b64 %0,{%1,%1};" : "=l"(r) : "f"(x)); return r;
}
__device__ __forceinline__ u64 ffma2(u64 a, u64 b, u64 c) {
    u64 d; asm("fma.rn.f32x2 %0,%1,%2,%3;" : "=l"(d) : "l"(a), "l"(b), "l"(c)); return d;
}
__device__ __forceinline__ float2 upk(u64 a) {
    float2 f; asm("mov.b64 {%0,%1},%2;" : "=f"(f.x), "=f"(f.y) : "l"(a)); return f;
}
__device__ __forceinline__ float frcp(float x) {
    float r; asm("rcp.approx.f32 %0,%1;" : "=f"(r) : "f"(x)); return r;
}

// ---------------- FMA-pipe exp2 (deg-7 Horner, rel err ~1e-8) -------------
__device__ __forceinline__ float fexp2(float y) {
    float k = y + 12582912.0f;              // RN round-to-int via magic
    float f = y - (k - 12582912.0f);        // f in [-0.5, 0.5], exact
    float p =            1.5252734e-5f;
    p = fmaf(p, f, 1.5403530e-4f);
    p = fmaf(p, f, 1.3333558e-3f);
    p = fmaf(p, f, 9.6181291e-3f);
    p = fmaf(p, f, 5.5504109e-2f);
    p = fmaf(p, f, 2.4022651e-1f);
    p = fmaf(p, f, 6.9314718e-1f);
    p = fmaf(p, f, 1.0f);
    float sc = __int_as_float((__float_as_int(k) - 1262485377) << 23);
    return p * sc;
}

// exp(2x), clamped to finite fp32 range
__device__ __forceinline__ float fexp2e(float x) {
    float y = fminf(fmaxf(x * 2.8853901f, -126.0f), 126.0f);  // 2*log2(e)*x
    return fexp2(y);
}

// scalar tanh (cell + pointer logits); rel err ~1e-7
__device__ __forceinline__ float fast_tanh(float x) {
    float ax = fabsf(x);
    float y  = fminf(ax * 2.8853901f, 126.0f);
    float e2 = fexp2(y);
    float r  = 1.0f - __fdividef(2.0f, e2 + 1.0f);
    return copysignf(r, x);
}
__device__ __forceinline__ float sigm(float x) {
    float y = fminf(fmaxf(-x * 1.4426950f, -126.0f), 126.0f);
    return __fdividef(1.0f, 1.0f + fexp2(y));
}

// ---------------- init ---------------------------------------------------
__global__ void k_init(const float* __restrict__ dec, const float* __restrict__ h0,
                       const float* __restrict__ c0) {
    int i = blockIdx.x * blockDim.x + threadIdx.x;
    if (i < BB * KK2) {
        int b = i >> 9, k = i & 511;
        g_xh0[i] = (k < EE) ? dec[b * EE + k] : h0[b * HH + (k - EE)];
    }
    if (i < BB * HH)  g_c[i] = c0[i];
    if (i < BB * LLN) g_mask[i] = 0;
}

// ---------------- weight prep (one-time) ----------------------------------
__global__ void k_prep_lstm(const float* __restrict__ Wih, const float* __restrict__ Whh,
                            const float* __restrict__ bih, const float* __restrict__ bhh) {
    int r = blockIdx.x;
    int j = r >> 2, g = r & 3;
    int src = g * HH + j;
    for (int k = threadIdx.x; k < EE; k += blockDim.x)
        g_Wc[(size_t)r * KK2 + k] = Wih[(size_t)src * EE + k];
    for (int k = threadIdx.x; k < HH; k += blockDim.x)
        g_Wc[(size_t)r * KK2 + EE + k] = Whh[(size_t)src * HH + k];
    if (threadIdx.x == 0) g_bc[r] = bih[src] + bhh[src];
}

// ---------------- generic NT GEMM with G->reg prefetch + PDL ---------------
// EXPF != 0 -> epilogue stores exp(2*(acc+bias)) instead of acc+bias.
struct GA { const float* A; int lda; const float* W; int wlda;
            const float* bias; float* C; };

template <int BM, int BN, int BK, int TM, int TN, int EXPF>
__global__ void gemm_multi(GA a0, GA a1, int N, int K) {
    constexpr int THREADS = (BM / TM) * (BN / TN);
    constexpr int A_LDS = BM * BK / THREADS / 4;
    constexpr int W_LDS = BN * BK / THREADS / 4;

    GA g = (blockIdx.z == 0) ? a0 : a1;

    __shared__ __align__(16) float As[BK][BM];
    __shared__ __align__(16) float Ws[BK][BN];

    const int tid = threadIdx.x;
    const int tx  = tid % (BN / TN);
    const int ty  = tid / (BN / TN);
    const int m0  = blockIdx.y * BM;
    const int n0  = blockIdx.x * BN;

    u64 acc[TM][TN / 2];
#pragma unroll
    for (int i = 0; i < TM; i++)
#pragma unroll
        for (int j = 0; j < TN / 2; j++) acc[i][j] = pk2(0.f, 0.f);

    float4 pa[A_LDS], pw[W_LDS];
    // W is a constant input weight -> safe before the grid-dependency wait
#pragma unroll
    for (int i = 0; i < W_LDS; i++) {
        int li = tid + i * THREADS;
        pw[i] = *(const float4*)(g.W + (size_t)(n0 + li / (BK / 4)) * g.wlda + (li % (BK / 4)) * 4);
    }
    gdep_wait();                          // A may be written by immediate predecessor
#pragma unroll
    for (int i = 0; i < A_LDS; i++) {
        int li = tid + i * THREADS;
        pa[i] = *(const float4*)(g.A + (size_t)(m0 + li / (BK / 4)) * g.lda + (li % (BK / 4)) * 4);
    }

    for (int k0 = 0; k0 < K; k0 += BK) {
#pragma unroll
        for (int i = 0; i < A_LDS; i++) {
            int li = tid + i * THREADS;
            int r = li / (BK / 4), c4 = li % (BK / 4);
            As[c4 * 4 + 0][r] = pa[i].x; As[c4 * 4 + 1][r] = pa[i].y;
            As[c4 * 4 + 2][r] = pa[i].z; As[c4 * 4 + 3][r] = pa[i].w;
        }
#pragma unroll
        for (int i = 0; i < W_LDS; i++) {
            int li = tid + i * THREADS;
            int r = li / (BK / 4), c4 = li % (BK / 4);
            Ws[c4 * 4 + 0][r] = pw[i].x; Ws[c4 * 4 + 1][r] = pw[i].y;
            Ws[c4 * 4 + 2][r] = pw[i].z; Ws[c4 * 4 + 3][r] = pw[i].w;
        }
        __syncthreads();

        if (k0 + BK < K) {
#pragma unroll
            for (int i = 0; i < A_LDS; i++) {
                int li = tid + i * THREADS;
                pa[i] = *(const float4*)(g.A + (size_t)(m0 + li / (BK / 4)) * g.lda
                                         + k0 + BK + (li % (BK / 4)) * 4);
            }
#pragma unroll
            for (int i = 0; i < W_LDS; i++) {
                int li = tid + i * THREADS;
                pw[i] = *(const float4*)(g.W + (size_t)(n0 + li / (BK / 4)) * g.wlda
                                         + k0 + BK + (li % (BK / 4)) * 4);
            }
        }

#pragma unroll
        for (int kk = 0; kk < BK; kk++) {
            u64 bp[TN / 2];
#pragma unroll
            for (int j = 0; j < TN / 4; j++) {
                float4 wv = *(const float4*)&Ws[kk][tx * TN + j * 4];
                bp[2 * j]     = pk2(wv.x, wv.y);
                bp[2 * j + 1] = pk2(wv.z, wv.w);
            }
#pragma unroll
            for (int i = 0; i < TM; i += 4) {
                float4 av = *(const float4*)&As[kk][ty * TM + i];
                u64 q0 = pkdup(av.x), q1 = pkdup(av.y), q2 = pkdup(av.z), q3 = pkdup(av.w);
#pragma unroll
                for (int j = 0; j < TN / 2; j++) {
                    acc[i + 0][j] = ffma2(q0, bp[j], acc[i + 0][j]);
                    acc[i + 1][j] = ffma2(q1, bp[j], acc[i + 1][j]);
                    acc[i + 2][j] = ffma2(q2, bp[j], acc[i + 2][j]);
                    acc[i + 3][j] = ffma2(q3, bp[j], acc[i + 3][j]);
                }
            }
        }
        __syncthreads();
    }

    const int n = n0 + tx * TN;
    float bb[TN];
#pragma unroll
    for (int j = 0; j < TN; j++) bb[j] = g.bias[n + j];
#pragma unroll
    for (int i = 0; i < TM; i++) {
        int m = m0 + ty * TM + i;
#pragma unroll
        for (int j = 0; j < TN / 4; j++) {
            float2 u0 = upk(acc[i][2 * j]);
            float2 u1 = upk(acc[i][2 * j + 1]);
            float4 r;
            r.x = u0.x + bb[4 * j];     r.y = u0.y + bb[4 * j + 1];
            r.z = u1.x + bb[4 * j + 2]; r.w = u1.y + bb[4 * j + 3];
            if (EXPF) {
                r.x = fexp2e(r.x); r.y = fexp2e(r.y);
                r.z = fexp2e(r.z); r.w = fexp2e(r.w);
            }
            *(float4*)(g.C + (size_t)m * N + n + 4 * j) = r;
        }
    }
    gdep_launch();                        // after C stores
}

// ---------------- LSTM gates, split-K x4 (R7-proven config) + PDL ----------
__global__ void k_lstm4(const float* __restrict__ A0) {
    constexpr int BM = 64, BN = 64, BK = 16, TM = 8;
    constexpr int THREADS = 128;

    __shared__ __align__(16) float As[BK][BM];
    __shared__ __align__(16) float Ws[BK][BN];

    const int tid = threadIdx.x;
    const int tx  = tid % 16;           // BN/TN
    const int ty  = tid / 16;
    const int m0  = blockIdx.y * BM;
    const int n0  = blockIdx.x * BN;
    const int z   = blockIdx.z;

    const float* A = A0 + z * KSEG;          // row stride KK2
    const float* W = g_Wc + z * KSEG;        // row stride KK2
    float* C = g_G + (size_t)z * BB * H4;

    u64 acc[TM][2];
#pragma unroll
    for (int i = 0; i < TM; i++) { acc[i][0] = pk2(0.f, 0.f); acc[i][1] = pk2(0.f, 0.f); }

    float4 pa[2], pw[2];
    // W (g_Wc) is many kernels old -> safe before wait
#pragma unroll
    for (int i = 0; i < 2; i++) {
        int li = tid + i * THREADS;
        pw[i] = *(const float4*)(W + (size_t)(n0 + li / 4) * KK2 + (li % 4) * 4);
    }
    gdep_wait();                          // xh written by immediate pred chain
#pragma unroll
    for (int i = 0; i < 2; i++) {
        int li = tid + i * THREADS;
        pa[i] = *(const float4*)(A + (size_t)(m0 + li / 4) * KK2 + (li % 4) * 4);
    }

    for (int k0 = 0; k0 < KSEG; k0 += BK) {
#pragma unroll
        for (int i = 0; i < 2; i++) {
            int li = tid + i * THREADS;
            int r = li / 4, c4 = li % 4;
            As[c4 * 4 + 0][r] = pa[i].x; As[c4 * 4 + 1][r] = pa[i].y;
            As[c4 * 4 + 2][r] = pa[i].z; As[c4 * 4 + 3][r] = pa[i].w;
            Ws[c4 * 4 + 0][r] = pw[i].x; Ws[c4 * 4 + 1][r] = pw[i].y;
            Ws[c4 * 4 + 2][r] = pw[i].z; Ws[c4 * 4 + 3][r] = pw[i].w;
        }
        __syncthreads();

        if (k0 + BK < KSEG) {
#pragma unroll
            for (int i = 0; i < 2; i++) {
                int li = tid + i * THREADS;
                pa[i] = *(const float4*)(A + (size_t)(m0 + li / 4) * KK2
                                         + k0 + BK + (li % 4) * 4);
                pw[i] = *(const float4*)(W + (size_t)(n0 + li / 4) * KK2
                                         + k0 + BK + (li % 4) * 4);
            }
        }

#pragma unroll
        for (int kk = 0; kk < BK; kk++) {
            float4 bv = *(const float4*)&Ws[kk][tx * 4];
            u64 bp0 = pk2(bv.x, bv.y);
            u64 bp1 = pk2(bv.z, bv.w);
#pragma unroll
            for (int i = 0; i < TM; i += 4) {
                float4 av = *(const float4*)&As[kk][ty * TM + i];
                u64 q0 = pkdup(av.x), q1 = pkdup(av.y), q2 = pkdup(av.z), q3 = pkdup(av.w);
                acc[i + 0][0] = ffma2(q0, bp0, acc[i + 0][0]);
                acc[i + 0][1] = ffma2(q0, bp1, acc[i + 0][1]);
                acc[i + 1][0] = ffma2(q1, bp0, acc[i + 1][0]);
                acc[i + 1][1] = ffma2(q1, bp1, acc[i + 1][1]);
                acc[i + 2][0] = ffma2(q2, bp0, acc[i + 2][0]);
                acc[i + 2][1] = ffma2(q2, bp1, acc[i + 2][1]);
                acc[i + 3][0] = ffma2(q3, bp0, acc[i + 3][0]);
                acc[i + 3][1] = ffma2(q3, bp1, acc[i + 3][1]);
            }
        }
        __syncthreads();
    }

    const int n = n0 + tx * 4;
#pragma unroll
    for (int i = 0; i < TM; i++) {
        int m = m0 + ty * TM + i;
        float2 u0 = upk(acc[i][0]);
        float2 u1 = upk(acc[i][1]);
        float4 r; r.x = u0.x; r.y = u0.y; r.z = u1.x; r.w = u1.y;
        *(float4*)(C + (size_t)m * H4 + n) = r;
    }
    gdep_launch();                        // after partial stores
}

// ---------------- LSTM cell: sum 4 split-K partials + nonlinearity ---------
__global__ void k_cell(float* __restrict__ xh_next) {
    gdep_wait();                          // g_G from immediate pred
    int b = blockIdx.x, j = threadIdx.x;  // 1024 x 256
    size_t off = (size_t)b * H4 + 4 * j;
    const float4 p0 = *(const float4*)(g_G + off);
    const float4 p1 = *(const float4*)(g_G + (size_t)1 * BB * H4 + off);
    const float4 p2 = *(const float4*)(g_G + (size_t)2 * BB * H4 + off);
    const float4 p3 = *(const float4*)(g_G + (size_t)3 * BB * H4 + off);
    const float4 bc = *(const float4*)(g_bc + 4 * j);
    float gi = (p0.x + p1.x) + (p2.x + p3.x) + bc.x;
    float gf = (p0.y + p1.y) + (p2.y + p3.y) + bc.y;
    float gg = (p0.z + p1.z) + (p2.z + p3.z) + bc.z;
    float go = (p0.w + p1.w) + (p2.w + p3.w) + bc.w;
    float c  = g_c[(size_t)b * HH + j];
    float c2 = sigm(gf) * c + sigm(gi) * fast_tanh(gg);
    g_c[(size_t)b * HH + j] = c2;
    xh_next[(size_t)b * KK2 + EE + j] = sigm(go) * fast_tanh(c2);
    gdep_launch();                        // after h/c stores
}

// ------ glimpse attention: exp-form u-pass, softmax, log-combine -> g ------
__global__ void k_attn_gl(const float* __restrict__ v) {
    int b = blockIdx.x, tid = threadIdx.x, lane = tid & 31, w = tid >> 5;
    __shared__ __align__(16) float qs[HH], vs[HH];
    __shared__ float sp[LLN];
    __shared__ float s_inv;
    vs[tid] = v[tid];                     // const input: safe pre-wait
    gdep_wait();                          // q from immediate pred (q_gl gemm)
    qs[tid] = g_qgl0[(size_t)b * HH + tid] + g_qgl1[(size_t)b * HH + tid];
    __syncthreads();

    const float* eb = g_e_gl + (size_t)b * HH;
    float4 Q0 = ((const float4*)qs)[lane * 2], Q1 = ((const float4*)qs)[lane * 2 + 1];
    Q0.x = fexp2e(Q0.x); Q0.y = fexp2e(Q0.y); Q0.z = fexp2e(Q0.z); Q0.w = fexp2e(Q0.w);
    Q1.x = fexp2e(Q1.x); Q1.y = fexp2e(Q1.y); Q1.z = fexp2e(Q1.z); Q1.w = fexp2e(Q1.w);
    float4 v0 = ((const float4*)vs)[lane * 2], v1 = ((const float4*)vs)[lane * 2 + 1];
    float sv = ((v0.x + v0.y) + (v0.z + v0.w)) + ((v1.x + v1.y) + (v1.z + v1.w));
#pragma unroll
    for (int o = 16; o; o >>= 1) sv += __shfl_xor_sync(0xffffffffu, sv, o);

    float s[7];
    float4 ebuf[7];
#pragma unroll
    for (int i = 0; i < 7; i++) {                 // batch 7 independent L2 loads
        int l = w + 8 * i; int lc = (l < LLN) ? l : (LLN - 1);
        ebuf[i] = ((const float4*)(eb + (size_t)lc * BB * HH))[lane * 2];
    }
#pragma unroll
    for (int i = 0; i < 7; i++) {
        float r;
        r = frcp(fmaf(Q0.x, ebuf[i].x, 1.f)); s[i] = v0.x * r;
        r = frcp(fmaf(Q0.y, ebuf[i].y, 1.f)); s[i] = fmaf(v0.y, r, s[i]);
        r = frcp(fmaf(Q0.z, ebuf[i].z, 1.f)); s[i] = fmaf(v0.z, r, s[i]);
        r = frcp(fmaf(Q0.w, ebuf[i].w, 1.f)); s[i] = fmaf(v0.w, r, s[i]);
    }
#pragma unroll
    for (int i = 0; i < 7; i++) {
        int l = w + 8 * i; int lc = (l < LLN) ? l : (LLN - 1);
        ebuf[i] = ((const float4*)(eb + (size_t)lc * BB * HH))[lane * 2 + 1];
    }
#pragma unroll
    for (int i = 0; i < 7; i++) {
        float r;
        r = frcp(fmaf(Q1.x, ebuf[i].x, 1.f)); s[i] = fmaf(v1.x, r, s[i]);
        r = frcp(fmaf(Q1.y, ebuf[i].y, 1.f)); s[i] = fmaf(v1.y, r, s[i]);
        r = frcp(fmaf(Q1.z, ebuf[i].z, 1.f)); s[i] = fmaf(v1.z, r, s[i]);
        r = frcp(fmaf(Q1.w, ebuf[i].w, 1.f)); s[i] = fmaf(v1.w, r, s[i]);
    }
#pragma unroll
    for (int o = 16; o; o >>= 1)
#pragma unroll
        for (int i = 0; i < 7; i++) s[i] += __shfl_xor_sync(0xffffffffu, s[i], o);
    if (lane == 0) {
#pragma unroll
        for (int i = 0; i < 7; i++) {
            int l = w + 8 * i;
            if (l < LLN) sp[l] = g_mask[b * LLN + l] ? NEGV : fmaf(-2.f, s[i], sv);
        }
    }
    __syncthreads();
    if (w == 0) {
        float a  = (lane < LLN) ? sp[lane] : -FLT_MAX;
        float bb = (lane + 32 < LLN) ? sp[lane + 32] : -FLT_MAX;
        float m = fmaxf(a, bb);
#pragma unroll
        for (int o = 16; o; o >>= 1) m = fmaxf(m, __shfl_xor_sync(0xffffffffu, m, o));
        float ea  = (lane < LLN) ? __expf(a - m) : 0.f;
        float eb2 = (lane + 32 < LLN) ? __expf(bb - m) : 0.f;
        if (lane < LLN) sp[lane] = ea;
        if (lane + 32 < LLN) sp[lane + 32] = eb2;
        float ssum = ea + eb2;
#pragma unroll
        for (int o = 16; o; o >>= 1) ssum += __shfl_xor_sync(0xffffffffu, ssum, o);
        if (lane == 0) s_inv = __fdividef(1.f, ssum);
    }
    __syncthreads();
    float inv = s_inv;
    // combine: e = 0.5*ln(E); g = 0.5*inv * sum_l sp[l]*ln(E[l])
    const float* ec = eb + tid;
    float a0 = 0.f, a1 = 0.f;
#pragma unroll
    for (int l = 0; l < LLN; l += 2) {
        a0 = fmaf(sp[l],     __logf(ec[(size_t) l      * BB * HH]), a0);
        a1 = fmaf(sp[l + 1], __logf(ec[(size_t)(l + 1) * BB * HH]), a1);
    }
    g_g[(size_t)b * HH + tid] = (a0 + a1) * (0.5f * inv);
    gdep_launch();                        // after g stores
}

// ---- pointer attention: exp-form u-pass, log_softmax, argmax, gather ------
__global__ void k_attn_pt(const float* __restrict__ v, const float* __restrict__ emb,
                          float* __restrict__ out, float* __restrict__ sel_out,
                          int t, int wsel, float* __restrict__ xh_next) {
    int b = blockIdx.x, tid = threadIdx.x, lane = tid & 31, w = tid >> 5;
    __shared__ __align__(16) float qs[HH], vs[HH];
    __shared__ float sp[LLN];
    __shared__ float s_lse;
    __shared__ int s_idx;
    vs[tid] = v[tid];                     // const input: safe pre-wait
    gdep_wait();                          // q from immediate pred (q_pt gemm)
    qs[tid] = g_qpt0[(size_t)b * HH + tid] + g_qpt1[(size_t)b * HH + tid];
    __syncthreads();

    const float* eb = g_e_pt + (size_t)b * HH;
    float4 Q0 = ((const float4*)qs)[lane * 2], Q1 = ((const float4*)qs)[lane * 2 + 1];
    Q0.x = fexp2e(Q0.x); Q0.y = fexp2e(Q0.y); Q0.z = fexp2e(Q0.z); Q0.w = fexp2e(Q0.w);
    Q1.x = fexp2e(Q1.x); Q1.y = fexp2e(Q1.y); Q1.z = fexp2e(Q1.z); Q1.w = fexp2e(Q1.w);
    float4 v0 = ((const float4*)vs)[lane * 2], v1 = ((const float4*)vs)[lane * 2 + 1];
    float sv = ((v0.x + v0.y) + (v0.z + v0.w)) + ((v1.x + v1.y) + (v1.z + v1.w));
#pragma unroll
    for (int o = 16; o; o >>= 1) sv += __shfl_xor_sync(0xffffffffu, sv, o);

    float s[7];
    float4 ebuf[7];
#pragma unroll
    for (int i = 0; i < 7; i++) {
        int l = w + 8 * i; int lc = (l < LLN) ? l : (LLN - 1);
        ebuf[i] = ((const float4*)(eb + (size_t)lc * BB * HH))[lane * 2];
    }
#pragma unroll
    for (int i = 0; i < 7; i++) {
        float r;
        r = frcp(fmaf(Q0.x, ebuf[i].x, 1.f)); s[i] = v0.x * r;
        r = frcp(fmaf(Q0.y, ebuf[i].y, 1.f)); s[i] = fmaf(v0.y, r, s[i]);
        r = frcp(fmaf(Q0.z, ebuf[i].z, 1.f)); s[i] = fmaf(v0.z, r, s[i]);
        r = frcp(fmaf(Q0.w, ebuf[i].w, 1.f)); s[i] = fmaf(v0.w, r, s[i]);
    }
#pragma unroll
    for (int i = 0; i < 7; i++) {
        int l = w + 8 * i; int lc = (l < LLN) ? l : (LLN - 1);
        ebuf[i] = ((const float4*)(eb + (size_t)lc * BB * HH))[lane * 2 + 1];
    }
#pragma unroll
    for (int i = 0; i < 7; i++) {
        float r;
        r = frcp(fmaf(Q1.x, ebuf[i].x, 1.f)); s[i] = fmaf(v1.x, r, s[i]);
        r = frcp(fmaf(Q1.y, ebuf[i].y, 1.f)); s[i] = fmaf(v1.y, r, s[i]);
        r = frcp(fmaf(Q1.z, ebuf[i].z, 1.f)); s[i] = fmaf(v1.z, r, s[i]);
        r = frcp(fmaf(Q1.w, ebuf[i].w, 1.f)); s[i] = fmaf(v1.w, r, s[i]);
    }
#pragma unroll
    for (int o = 16; o; o >>= 1)
#pragma unroll
        for (int i = 0; i < 7; i++) s[i] += __shfl_xor_sync(0xffffffffu, s[i], o);
    if (lane == 0) {
#pragma unroll
        for (int i = 0; i < 7; i++) {
            int l = w + 8 * i;
            if (l < LLN)
                sp[l] = g_mask[b * LLN + l] ? NEGV
                                            : (CEXPL * fast_tanh(fmaf(-2.f, s[i], sv)));
        }
    }
    __syncthreads();
    if (w == 0) {
        float a  = (lane < LLN) ? sp[lane] : -FLT_MAX;           int ia = lane;
        float bb = (lane + 32 < LLN) ? sp[lane + 32] : -FLT_MAX; int ib = lane + 32;
        float m; int mi;
        if (bb > a) { m = bb; mi = ib; } else { m = a; mi = ia; }
#pragma unroll
        for (int o = 16; o; o >>= 1) {
            float om = __shfl_xor_sync(0xffffffffu, m, o);
            int   oi = __shfl_xor_sync(0xffffffffu, mi, o);
            if (om > m || (om == m && oi < mi)) { m = om; mi = oi; }
        }
        float ssum = ((lane < LLN) ? __expf(a - m) : 0.f)
                   + ((lane + 32 < LLN) ? __expf(bb - m) : 0.f);
#pragma unroll
        for (int o = 16; o; o >>= 1) ssum += __shfl_xor_sync(0xffffffffu, ssum, o);
        if (lane == 0) { s_lse = m + __logf(ssum); s_idx = mi; }
    }
    __syncthreads();
    int idx = s_idx; float lse = s_lse;
    if (tid < LLN)
        out[((size_t)b * LLN + t) * LLN + tid] = sp[tid] - lse;
    xh_next[(size_t)b * KK2 + tid] = emb[((size_t)idx * BB + b) * EE + tid];
    if (tid == 0) {
        g_mask[b * LLN + idx] = 1;       // mask for NEXT step
        int cnt = 0;
#pragma unroll
        for (int l = 0; l < LLN; l++) cnt += g_mask[b * LLN + l];
        if (cnt == LLN) g_mask[b * LLN + LLN - 1] = 0;   // ref's all-true reset
        if (wsel) sel_out[b * LLN + t] = (float)idx;
    }
    gdep_launch();                        // after all stores (x, mask, out)
}

// -------------------------------- launch ----------------------------------
extern "C" void kernel_launch(void* const* d_in, const int* in_sizes, int n_in,
                              void* d_out, int out_size) {
    (void)in_sizes; (void)n_in;
    const float* dec  = (const float*)d_in[0];
    const float* emb  = (const float*)d_in[1];
    const float* h0   = (const float*)d_in[2];
    const float* c0   = (const float*)d_in[3];
    const float* ctx  = (const float*)d_in[4];
    const float* Wih  = (const float*)d_in[6];
    const float* Whh  = (const float*)d_in[7];
    const float* bih  = (const float*)d_in[8];
    const float* bhh  = (const float*)d_in[9];
    const float* glWq = (const float*)d_in[10];
    const float* glbq = (const float*)d_in[11];
    const float* glWr = (const float*)d_in[12];
    const float* glbr = (const float*)d_in[13];
    const float* glv  = (const float*)d_in[14];
    const float* ptWq = (const float*)d_in[15];
    const float* ptbq = (const float*)d_in[16];
    const float* ptWr = (const float*)d_in[17];
    const float* ptbr = (const float*)d_in[18];
    const float* ptv  = (const float*)d_in[19];
    float* out = (float*)d_out;

    float *pe_gl, *pe_pt, *pxh0, *pxh1, *pg, *pzero;
    float *pqgl0, *pqgl1, *pqpt0, *pqpt1;
    cudaGetSymbolAddress((void**)&pe_gl, g_e_gl);
    cudaGetSymbolAddress((void**)&pe_pt, g_e_pt);
    cudaGetSymbolAddress((void**)&pxh0,  g_xh0);
    cudaGetSymbolAddress((void**)&pxh1,  g_xh1);
    cudaGetSymbolAddress((void**)&pg,    g_g);
    cudaGetSymbolAddress((void**)&pzero, g_zero);
    cudaGetSymbolAddress((void**)&pqgl0, g_qgl0);
    cudaGetSymbolAddress((void**)&pqgl1, g_qgl1);
    cudaGetSymbolAddress((void**)&pqpt0, g_qpt0);
    cudaGetSymbolAddress((void**)&pqpt1, g_qpt1);

    // PDL launch config (programmatic stream serialization)
    cudaLaunchAttribute pdlAttr{};
    pdlAttr.id = cudaLaunchAttributeProgrammaticStreamSerialization;
    pdlAttr.val.programmaticStreamSerializationAllowed = 1;
    auto mkcfg = [&](dim3 g, dim3 b) {
        cudaLaunchConfig_t c{};
        c.gridDim = g; c.blockDim = b; c.dynamicSmemBytes = 0;
        c.stream = 0; c.attrs = &pdlAttr; c.numAttrs = 1;
        return c;
    };

    k_init<<<2048, 256>>>(dec, h0, c0);
    k_prep_lstm<<<H4, 256>>>(Wih, Whh, bih, bhh);

    // Time-invariant projections WITH fused exp: E_gl = exp(2*(ctx@glWr^T+glbr)),
    // E_pt = exp(2*(ctx@ptWr^T+ptbr)). R7-ratio tile (TM8/TN4, 96 regs), 3200 CTAs.
    {
        GA a0{ctx, HH, glWr, HH, glbr, pe_gl};
        GA a1{ctx, HH, ptWr, HH, ptbr, pe_pt};
        cudaLaunchConfig_t c = mkcfg(dim3(HH / 64, (LLN * BB) / 128, 2), dim3(256));
        cudaLaunchKernelEx(&c, gemm_multi<128, 64, 16, 8, 4, 1>, a0, a1, (int)HH, (int)HH);
    }

    const size_t BLLL = (size_t)BB * LLN * LLN;
    const int wsel = (out_size >= (int)(BLLL + (size_t)BB * LLN)) ? 1 : 0;

    float* xh[2] = {pxh0, pxh1};
    for (int t = 0; t < LLN; t++) {
        float* cur = xh[t & 1];
        float* nxt = xh[(t + 1) & 1];
        // LSTM gates, split-K x4 -> g_G[0..3]; 1024 CTAs of 128 thr (R7 config)
        {
            cudaLaunchConfig_t c = mkcfg(dim3(H4 / 64, BB / 64, KSPLIT), dim3(128));
            cudaLaunchKernelEx(&c, k_lstm4, (const float*)cur);
        }
        // cell: sum partials, nonlinearity, h_t -> nxt[:,256:512]
        {
            cudaLaunchConfig_t c = mkcfg(dim3(BB), dim3(HH));
            cudaLaunchKernelEx(&c, k_cell, nxt);
        }
        // q_gl split-K x2 (bias in z=0; partials summed in k_attn_gl)
        {
            GA a0{nxt + EE,       KK2, glWq,       HH, glbq,  pqgl0};
            GA a1{nxt + EE + 128, KK2, glWq + 128, HH, pzero, pqgl1};
            cudaLaunchConfig_t c = mkcfg(dim3(HH / 64, BB / 32, 2), dim3(128));
            cudaLaunchKernelEx(&c, gemm_multi<32, 64, 16, 4, 4, 0>, a0, a1, (int)HH, 128);
        }
        // glimpse attention -> g
        {
            cudaLaunchConfig_t c = mkcfg(dim3(BB), dim3(HH));
            cudaLaunchKernelEx(&c, k_attn_gl, glv);
        }
        // q_pt split-K x2
        {
            GA a0{pg,       HH, ptWq,       HH, ptbq,  pqpt0};
            GA a1{pg + 128, HH, ptWq + 128, HH, pzero, pqpt1};
            cudaLaunchConfig_t c = mkcfg(dim3(HH / 64, BB / 32, 2), dim3(128));
            cudaLaunchKernelEx(&c, gemm_multi<32, 64, 16, 4, 4, 0>, a0, a1, (int)HH, 128);
        }
        // pointer attention: log_p -> out, argmax, gather x_{t+1}, mask update
        {
            cudaLaunchConfig_t c = mkcfg(dim3(BB), dim3(HH));
            cudaLaunchKernelEx(&c, k_attn_pt, ptv, emb, out, out + BLLL, t, wsel, nxt);
        }
    }
}

// round 17
// speedup vs baseline: 1.2104x; 1.0069x over previous
#include <cuda_runtime.h>
#include <math.h>
#include <float.h>

#define BB 1024
#define LLN 50
#define EE 256
#define HH 256
#define KK2 512          // E + H (Wc row length)
#define H4 1024
#define NEGV (-1e9f)
#define CEXPL 10.0f
#define KSPLIT 4
#define KSEGH (HH / KSPLIT)   // 64: h-only split-K segment

typedef unsigned long long u64;

// ---------------- device scratch (no allocations allowed) ----------------
// g_e_gl / g_e_pt hold exp(2*e) (written directly by the precompute epilogue).
__device__ __align__(16) float g_e_gl[(size_t)LLN * BB * HH];  // 52.4 MB
__device__ __align__(16) float g_e_pt[(size_t)LLN * BB * HH];  // 52.4 MB
__device__ __align__(16) float g_Gx [(size_t)LLN * BB * H4];   // 210 MB: emb@Wc_x^T
__device__ __align__(16) float g_Gx0[BB * H4];                 // dec@Wc_x^T
__device__ __align__(16) float g_h0 [BB * HH];                 // h ping
__device__ __align__(16) float g_h1 [BB * HH];                 // h pong
__device__ __align__(16) float g_c  [BB * HH];
__device__ __align__(16) float g_qgl0[BB * HH];
__device__ __align__(16) float g_qgl1[BB * HH];
__device__ __align__(16) float g_g   [BB * HH];
__device__ __align__(16) float g_qpt0[BB * HH];
__device__ __align__(16) float g_qpt1[BB * HH];
__device__ __align__(16) float g_G  [(size_t)KSPLIT * BB * H4]; // split-K partials
__device__ __align__(16) float g_Wc [H4 * KK2];                // gate-interleaved [Wih|Whh]
__device__ __align__(16) float g_bc [H4];
__device__ __align__(16) float g_zero[H4];                     // static zero bias
__device__ int g_idx[BB];
__device__ unsigned char g_mask[BB * LLN];

// ---------------- PDL intrinsics (sm_90+) ---------------------------------
// launch_dependents MUST execute only after all stores that dependents read.
__device__ __forceinline__ void gdep_wait()   { asm volatile("griddepcontrol.wait;" ::: "memory"); }
__device__ __forceinline__ void gdep_launch() { asm volatile("griddepcontrol.launch_dependents;" ::: "memory"); }

// ---------------- packed fp32x2 helpers (IEEE-exact per lane) -------------
__device__ __forceinline__ u64 pk2(float x, float y) {
    u64 r; asm("mov.b64 %0,{%1,%2};" : "=l"(r) : "f"(x), "f"(y)); return r;
}
__device__ __forceinline__ u64 pkdup(float x) {
    u64 r; asm("mov.b64 %0,{%1,%1};" : "=l"(r) : "f"(x)); return r;
}
__device__ __forceinline__ u64 ffma2(u64 a, u64 b, u64 c) {
    u64 d; asm("fma.rn.f32x2 %0,%1,%2,%3;" : "=l"(d) : "l"(a), "l"(b), "l"(c)); return d;
}
__device__ __forceinline__ float2 upk(u64 a) {
    float2 f; asm("mov.b64 {%0,%1},%2;" : "=f"(f.x), "=f"(f.y) : "l"(a)); return f;
}
__device__ __forceinline__ float frcp(float x) {
    float r; asm("rcp.approx.f32 %0,%1;" : "=f"(r) : "f"(x)); return r;
}

// ---------------- FMA-pipe exp2 (deg-7 Horner, rel err ~1e-8) -------------
__device__ __forceinline__ float fexp2(float y) {
    float k = y + 12582912.0f;              // RN round-to-int via magic
    float f = y - (k - 12582912.0f);        // f in [-0.5, 0.5], exact
    float p =            1.5252734e-5f;
    p = fmaf(p, f, 1.5403530e-4f);
    p = fmaf(p, f, 1.3333558e-3f);
    p = fmaf(p, f, 9.6181291e-3f);
    p = fmaf(p, f, 5.5504109e-2f);
    p = fmaf(p, f, 2.4022651e-1f);
    p = fmaf(p, f, 6.9314718e-1f);
    p = fmaf(p, f, 1.0f);
    float sc = __int_as_float((__float_as_int(k) - 1262485377) << 23);
    return p * sc;
}

// exp(2x), clamped to finite fp32 range
__device__ __forceinline__ float fexp2e(float x) {
    float y = fminf(fmaxf(x * 2.8853901f, -126.0f), 126.0f);  // 2*log2(e)*x
    return fexp2(y);
}

// scalar tanh (cell + pointer logits); rel err ~1e-7
__device__ __forceinline__ float fast_tanh(float x) {
    float ax = fabsf(x);
    float y  = fminf(ax * 2.8853901f, 126.0f);
    float e2 = fexp2(y);
    float r  = 1.0f - __fdividef(2.0f, e2 + 1.0f);
    return copysignf(r, x);
}
__device__ __forceinline__ float sigm(float x) {
    float y = fminf(fmaxf(-x * 1.4426950f, -126.0f), 126.0f);
    return __fdividef(1.0f, 1.0f + fexp2(y));
}

// ---------------- init ---------------------------------------------------
__global__ void k_init(const float* __restrict__ h0, const float* __restrict__ c0) {
    int i = blockIdx.x * blockDim.x + threadIdx.x;    // 1024*256
    if (i < BB * HH) { g_h0[i] = h0[i]; g_c[i] = c0[i]; }
    if (i < BB * LLN) g_mask[i] = 0;
}

// ---------------- weight prep (one-time) ----------------------------------
__global__ void k_prep_lstm(const float* __restrict__ Wih, const float* __restrict__ Whh,
                            const float* __restrict__ bih, const float* __restrict__ bhh) {
    int r = blockIdx.x;
    int j = r >> 2, g = r & 3;
    int src = g * HH + j;
    for (int k = threadIdx.x; k < EE; k += blockDim.x)
        g_Wc[(size_t)r * KK2 + k] = Wih[(size_t)src * EE + k];
    for (int k = threadIdx.x; k < HH; k += blockDim.x)
        g_Wc[(size_t)r * KK2 + EE + k] = Whh[(size_t)src * HH + k];
    if (threadIdx.x == 0) g_bc[r] = bih[src] + bhh[src];
}

// ---------------- generic NT GEMM with G->reg prefetch + PDL ---------------
// EXPF != 0 -> epilogue stores exp(2*(acc+bias)) instead of acc+bias.
struct GA { const float* A; int lda; const float* W; int wlda;
            const float* bias; float* C; };

template <int BM, int BN, int BK, int TM, int TN, int EXPF>
__global__ void gemm_multi(GA a0, GA a1, int N, int K) {
    constexpr int THREADS = (BM / TM) * (BN / TN);
    constexpr int A_LDS = BM * BK / THREADS / 4;
    constexpr int W_LDS = BN * BK / THREADS / 4;

    GA g = (blockIdx.z == 0) ? a0 : a1;

    __shared__ __align__(16) float As[BK][BM];
    __shared__ __align__(16) float Ws[BK][BN];

    const int tid = threadIdx.x;
    const int tx  = tid % (BN / TN);
    const int ty  = tid / (BN / TN);
    const int m0  = blockIdx.y * BM;
    const int n0  = blockIdx.x * BN;

    u64 acc[TM][TN / 2];
#pragma unroll
    for (int i = 0; i < TM; i++)
#pragma unroll
        for (int j = 0; j < TN / 2; j++) acc[i][j] = pk2(0.f, 0.f);

    float4 pa[A_LDS], pw[W_LDS];
    // W is constant (input weights) -> safe before the grid-dependency wait
#pragma unroll
    for (int i = 0; i < W_LDS; i++) {
        int li = tid + i * THREADS;
        pw[i] = *(const float4*)(g.W + (size_t)(n0 + li / (BK / 4)) * g.wlda + (li % (BK / 4)) * 4);
    }
    gdep_wait();                          // A may be written by immediate predecessor
#pragma unroll
    for (int i = 0; i < A_LDS; i++) {
        int li = tid + i * THREADS;
        pa[i] = *(const float4*)(g.A + (size_t)(m0 + li / (BK / 4)) * g.lda + (li % (BK / 4)) * 4);
    }

    for (int k0 = 0; k0 < K; k0 += BK) {
#pragma unroll
        for (int i = 0; i < A_LDS; i++) {
            int li = tid + i * THREADS;
            int r = li / (BK / 4), c4 = li % (BK / 4);
            As[c4 * 4 + 0][r] = pa[i].x; As[c4 * 4 + 1][r] = pa[i].y;
            As[c4 * 4 + 2][r] = pa[i].z; As[c4 * 4 + 3][r] = pa[i].w;
        }
#pragma unroll
        for (int i = 0; i < W_LDS; i++) {
            int li = tid + i * THREADS;
            int r = li / (BK / 4), c4 = li % (BK / 4);
            Ws[c4 * 4 + 0][r] = pw[i].x; Ws[c4 * 4 + 1][r] = pw[i].y;
            Ws[c4 * 4 + 2][r] = pw[i].z; Ws[c4 * 4 + 3][r] = pw[i].w;
        }
        __syncthreads();

        if (k0 + BK < K) {
#pragma unroll
            for (int i = 0; i < A_LDS; i++) {
                int li = tid + i * THREADS;
                pa[i] = *(const float4*)(g.A + (size_t)(m0 + li / (BK / 4)) * g.lda
                                         + k0 + BK + (li % (BK / 4)) * 4);
            }
#pragma unroll
            for (int i = 0; i < W_LDS; i++) {
                int li = tid + i * THREADS;
                pw[i] = *(const float4*)(g.W + (size_t)(n0 + li / (BK / 4)) * g.wlda
                                         + k0 + BK + (li % (BK / 4)) * 4);
            }
        }

#pragma unroll
        for (int kk = 0; kk < BK; kk++) {
            u64 bp[TN / 2];
#pragma unroll
            for (int j = 0; j < TN / 4; j++) {
                float4 wv = *(const float4*)&Ws[kk][tx * TN + j * 4];
                bp[2 * j]     = pk2(wv.x, wv.y);
                bp[2 * j + 1] = pk2(wv.z, wv.w);
            }
#pragma unroll
            for (int i = 0; i < TM; i += 4) {
                float4 av = *(const float4*)&As[kk][ty * TM + i];
                u64 q0 = pkdup(av.x), q1 = pkdup(av.y), q2 = pkdup(av.z), q3 = pkdup(av.w);
#pragma unroll
                for (int j = 0; j < TN / 2; j++) {
                    acc[i + 0][j] = ffma2(q0, bp[j], acc[i + 0][j]);
                    acc[i + 1][j] = ffma2(q1, bp[j], acc[i + 1][j]);
                    acc[i + 2][j] = ffma2(q2, bp[j], acc[i + 2][j]);
                    acc[i + 3][j] = ffma2(q3, bp[j], acc[i + 3][j]);
                }
            }
        }
        __syncthreads();
    }

    const int n = n0 + tx * TN;
    float bb[TN];
#pragma unroll
    for (int j = 0; j < TN; j++) bb[j] = g.bias[n + j];
#pragma unroll
    for (int i = 0; i < TM; i++) {
        int m = m0 + ty * TM + i;
#pragma unroll
        for (int j = 0; j < TN / 4; j++) {
            float2 u0 = upk(acc[i][2 * j]);
            float2 u1 = upk(acc[i][2 * j + 1]);
            float4 r;
            r.x = u0.x + bb[4 * j];     r.y = u0.y + bb[4 * j + 1];
            r.z = u1.x + bb[4 * j + 2]; r.w = u1.y + bb[4 * j + 3];
            if (EXPF) {
                r.x = fexp2e(r.x); r.y = fexp2e(r.y);
                r.z = fexp2e(r.z); r.w = fexp2e(r.w);
            }
            *(float4*)(g.C + (size_t)m * N + n + 4 * j) = r;
        }
    }
    gdep_launch();                        // after C stores
}

// ------- LSTM h-part gates, split-K x4 over K=256 (R7-ratio tile) ----------
// grid (16,16,4) = 1024 CTAs, 128 thr, TM8/TN4.
__global__ void k_lstmH(const float* __restrict__ H) {
    constexpr int BM = 64, BN = 64, BK = 16, TM = 8;
    constexpr int THREADS = 128;

    __shared__ __align__(16) float As[BK][BM];
    __shared__ __align__(16) float Ws[BK][BN];

    const int tid = threadIdx.x;
    const int tx  = tid % 16;           // BN/TN
    const int ty  = tid / 16;
    const int m0  = blockIdx.y * BM;
    const int n0  = blockIdx.x * BN;
    const int z   = blockIdx.z;

    const float* A = H + z * KSEGH;               // row stride HH
    const float* W = g_Wc + EE + z * KSEGH;       // h-part cols of Wc, row stride KK2
    float* C = g_G + (size_t)z * BB * H4;

    u64 acc[TM][2];
#pragma unroll
    for (int i = 0; i < TM; i++) { acc[i][0] = pk2(0.f, 0.f); acc[i][1] = pk2(0.f, 0.f); }

    float4 pa[2], pw[2];
    // W (g_Wc) is many kernels old -> safe before wait
#pragma unroll
    for (int i = 0; i < 2; i++) {
        int li = tid + i * THREADS;
        pw[i] = *(const float4*)(W + (size_t)(n0 + li / 4) * KK2 + (li % 4) * 4);
    }
    gdep_wait();                          // h written by pred chain
#pragma unroll
    for (int i = 0; i < 2; i++) {
        int li = tid + i * THREADS;
        pa[i] = *(const float4*)(A + (size_t)(m0 + li / 4) * HH + (li % 4) * 4);
    }

    for (int k0 = 0; k0 < KSEGH; k0 += BK) {
#pragma unroll
        for (int i = 0; i < 2; i++) {
            int li = tid + i * THREADS;
            int r = li / 4, c4 = li % 4;
            As[c4 * 4 + 0][r] = pa[i].x; As[c4 * 4 + 1][r] = pa[i].y;
            As[c4 * 4 + 2][r] = pa[i].z; As[c4 * 4 + 3][r] = pa[i].w;
            Ws[c4 * 4 + 0][r] = pw[i].x; Ws[c4 * 4 + 1][r] = pw[i].y;
            Ws[c4 * 4 + 2][r] = pw[i].z; Ws[c4 * 4 + 3][r] = pw[i].w;
        }
        __syncthreads();

        if (k0 + BK < KSEGH) {
#pragma unroll
            for (int i = 0; i < 2; i++) {
                int li = tid + i * THREADS;
                pa[i] = *(const float4*)(A + (size_t)(m0 + li / 4) * HH
                                         + k0 + BK + (li % 4) * 4);
                pw[i] = *(const float4*)(W + (size_t)(n0 + li / 4) * KK2
                                         + k0 + BK + (li % 4) * 4);
            }
        }

#pragma unroll
        for (int kk = 0; kk < BK; kk++) {
            float4 bv = *(const float4*)&Ws[kk][tx * 4];
            u64 bp0 = pk2(bv.x, bv.y);
            u64 bp1 = pk2(bv.z, bv.w);
#pragma unroll
            for (int i = 0; i < TM; i += 4) {
                float4 av = *(const float4*)&As[kk][ty * TM + i];
                u64 q0 = pkdup(av.x), q1 = pkdup(av.y), q2 = pkdup(av.z), q3 = pkdup(av.w);
                acc[i + 0][0] = ffma2(q0, bp0, acc[i + 0][0]);
                acc[i + 0][1] = ffma2(q0, bp1, acc[i + 0][1]);
                acc[i + 1][0] = ffma2(q1, bp0, acc[i + 1][0]);
                acc[i + 1][1] = ffma2(q1, bp1, acc[i + 1][1]);
                acc[i + 2][0] = ffma2(q2, bp0, acc[i + 2][0]);
                acc[i + 2][1] = ffma2(q2, bp1, acc[i + 2][1]);
                acc[i + 3][0] = ffma2(q3, bp0, acc[i + 3][0]);
                acc[i + 3][1] = ffma2(q3, bp1, acc[i + 3][1]);
            }
        }
        __syncthreads();
    }

    const int n = n0 + tx * 4;
#pragma unroll
    for (int i = 0; i < TM; i++) {
        int m = m0 + ty * TM + i;
        float2 u0 = upk(acc[i][0]);
        float2 u1 = upk(acc[i][1]);
        float4 r; r.x = u0.x; r.y = u0.y; r.z = u1.x; r.w = u1.y;
        *(float4*)(C + (size_t)m * H4 + n) = r;
    }
    gdep_launch();                        // after partial stores
}

// -------- LSTM cell: h-partials + gathered x-gates + nonlinearity ----------
__global__ void k_cell(int t, float* __restrict__ h_next) {
    gdep_wait();                          // g_G from immediate pred
    int b = blockIdx.x, j = threadIdx.x;  // 1024 x 256
    size_t off = (size_t)b * H4 + 4 * j;
    const float4 p0 = *(const float4*)(g_G + off);
    const float4 p1 = *(const float4*)(g_G + (size_t)1 * BB * H4 + off);
    const float4 p2 = *(const float4*)(g_G + (size_t)2 * BB * H4 + off);
    const float4 p3 = *(const float4*)(g_G + (size_t)3 * BB * H4 + off);
    // precomputed x-part gates: dec row at t=0, else emb[idx] row
    const float* gx = (t == 0) ? (g_Gx0 + (size_t)b * H4)
                               : (g_Gx + ((size_t)g_idx[b] * BB + b) * H4);
    const float4 px = *(const float4*)(gx + 4 * j);
    const float4 bc = *(const float4*)(g_bc + 4 * j);
    float gi = (p0.x + p1.x) + (p2.x + p3.x) + px.x + bc.x;
    float gf = (p0.y + p1.y) + (p2.y + p3.y) + px.y + bc.y;
    float gg = (p0.z + p1.z) + (p2.z + p3.z) + px.z + bc.z;
    float go = (p0.w + p1.w) + (p2.w + p3.w) + px.w + bc.w;
    float c  = g_c[(size_t)b * HH + j];
    float c2 = sigm(gf) * c + sigm(gi) * fast_tanh(gg);
    g_c[(size_t)b * HH + j] = c2;
    h_next[(size_t)b * HH + j] = sigm(go) * fast_tanh(c2);
    gdep_launch();                        // after h/c stores
}

// ------ glimpse attention: exp-form u-pass, softmax, log-combine -> g ------
__global__ void k_attn_gl(const float* __restrict__ v) {
    int b = blockIdx.x, tid = threadIdx.x, lane = tid & 31, w = tid >> 5;
    __shared__ __align__(16) float qs[HH], vs[HH];
    __shared__ float sp[LLN];
    __shared__ float s_inv;
    vs[tid] = v[tid];                     // const input: safe pre-wait
    gdep_wait();                          // q from immediate pred (q_gl gemm)
    qs[tid] = g_qgl0[(size_t)b * HH + tid] + g_qgl1[(size_t)b * HH + tid];
    __syncthreads();

    const float* eb = g_e_gl + (size_t)b * HH;
    float4 Q0 = ((const float4*)qs)[lane * 2], Q1 = ((const float4*)qs)[lane * 2 + 1];
    Q0.x = fexp2e(Q0.x); Q0.y = fexp2e(Q0.y); Q0.z = fexp2e(Q0.z); Q0.w = fexp2e(Q0.w);
    Q1.x = fexp2e(Q1.x); Q1.y = fexp2e(Q1.y); Q1.z = fexp2e(Q1.z); Q1.w = fexp2e(Q1.w);
    float4 v0 = ((const float4*)vs)[lane * 2], v1 = ((const float4*)vs)[lane * 2 + 1];
    float sv = ((v0.x + v0.y) + (v0.z + v0.w)) + ((v1.x + v1.y) + (v1.z + v1.w));
#pragma unroll
    for (int o = 16; o; o >>= 1) sv += __shfl_xor_sync(0xffffffffu, sv, o);

    float s[7];
    float4 ebuf[7];
#pragma unroll
    for (int i = 0; i < 7; i++) {                 // batch 7 independent L2 loads
        int l = w + 8 * i; int lc = (l < LLN) ? l : (LLN - 1);
        ebuf[i] = ((const float4*)(eb + (size_t)lc * BB * HH))[lane * 2];
    }
#pragma unroll
    for (int i = 0; i < 7; i++) {
        float r;
        r = frcp(fmaf(Q0.x, ebuf[i].x, 1.f)); s[i] = v0.x * r;
        r = frcp(fmaf(Q0.y, ebuf[i].y, 1.f)); s[i] = fmaf(v0.y, r, s[i]);
        r = frcp(fmaf(Q0.z, ebuf[i].z, 1.f)); s[i] = fmaf(v0.z, r, s[i]);
        r = frcp(fmaf(Q0.w, ebuf[i].w, 1.f)); s[i] = fmaf(v0.w, r, s[i]);
    }
#pragma unroll
    for (int i = 0; i < 7; i++) {
        int l = w + 8 * i; int lc = (l < LLN) ? l : (LLN - 1);
        ebuf[i] = ((const float4*)(eb + (size_t)lc * BB * HH))[lane * 2 + 1];
    }
#pragma unroll
    for (int i = 0; i < 7; i++) {
        float r;
        r = frcp(fmaf(Q1.x, ebuf[i].x, 1.f)); s[i] = fmaf(v1.x, r, s[i]);
        r = frcp(fmaf(Q1.y, ebuf[i].y, 1.f)); s[i] = fmaf(v1.y, r, s[i]);
        r = frcp(fmaf(Q1.z, ebuf[i].z, 1.f)); s[i] = fmaf(v1.z, r, s[i]);
        r = frcp(fmaf(Q1.w, ebuf[i].w, 1.f)); s[i] = fmaf(v1.w, r, s[i]);
    }
#pragma unroll
    for (int o = 16; o; o >>= 1)
#pragma unroll
        for (int i = 0; i < 7; i++) s[i] += __shfl_xor_sync(0xffffffffu, s[i], o);
    if (lane == 0) {
#pragma unroll
        for (int i = 0; i < 7; i++) {
            int l = w + 8 * i;
            if (l < LLN) sp[l] = g_mask[b * LLN + l] ? NEGV : fmaf(-2.f, s[i], sv);
        }
    }
    __syncthreads();
    if (w == 0) {
        float a  = (lane < LLN) ? sp[lane] : -FLT_MAX;
        float bb = (lane + 32 < LLN) ? sp[lane + 32] : -FLT_MAX;
        float m = fmaxf(a, bb);
#pragma unroll
        for (int o = 16; o; o >>= 1) m = fmaxf(m, __shfl_xor_sync(0xffffffffu, m, o));
        float ea  = (lane < LLN) ? __expf(a - m) : 0.f;
        float eb2 = (lane + 32 < LLN) ? __expf(bb - m) : 0.f;
        if (lane < LLN) sp[lane] = ea;
        if (lane + 32 < LLN) sp[lane + 32] = eb2;
        float ssum = ea + eb2;
#pragma unroll
        for (int o = 16; o; o >>= 1) ssum += __shfl_xor_sync(0xffffffffu, ssum, o);
        if (lane == 0) s_inv = __fdividef(1.f, ssum);
    }
    __syncthreads();
    float inv = s_inv;
    // combine: e = 0.5*ln(E); g = 0.5*inv * sum_l sp[l]*ln(E[l])
    const float* ec = eb + tid;
    float a0 = 0.f, a1 = 0.f;
#pragma unroll
    for (int l = 0; l < LLN; l += 2) {
        a0 = fmaf(sp[l],     __logf(ec[(size_t) l      * BB * HH]), a0);
        a1 = fmaf(sp[l + 1], __logf(ec[(size_t)(l + 1) * BB * HH]), a1);
    }
    g_g[(size_t)b * HH + tid] = (a0 + a1) * (0.5f * inv);
    gdep_launch();                        // after g stores
}

// ---- pointer attention: exp-form u-pass, log_softmax, argmax, mask --------
__global__ void k_attn_pt(const float* __restrict__ v,
                          float* __restrict__ out, float* __restrict__ sel_out,
                          int t, int wsel) {
    int b = blockIdx.x, tid = threadIdx.x, lane = tid & 31, w = tid >> 5;
    __shared__ __align__(16) float qs[HH], vs[HH];
    __shared__ float sp[LLN];
    __shared__ float s_lse;
    __shared__ int s_idx;
    vs[tid] = v[tid];                     // const input: safe pre-wait
    gdep_wait();                          // q from immediate pred (q_pt gemm)
    qs[tid] = g_qpt0[(size_t)b * HH + tid] + g_qpt1[(size_t)b * HH + tid];
    __syncthreads();

    const float* eb = g_e_pt + (size_t)b * HH;
    float4 Q0 = ((const float4*)qs)[lane * 2], Q1 = ((const float4*)qs)[lane * 2 + 1];
    Q0.x = fexp2e(Q0.x); Q0.y = fexp2e(Q0.y); Q0.z = fexp2e(Q0.z); Q0.w = fexp2e(Q0.w);
    Q1.x = fexp2e(Q1.x); Q1.y = fexp2e(Q1.y); Q1.z = fexp2e(Q1.z); Q1.w = fexp2e(Q1.w);
    float4 v0 = ((const float4*)vs)[lane * 2], v1 = ((const float4*)vs)[lane * 2 + 1];
    float sv = ((v0.x + v0.y) + (v0.z + v0.w)) + ((v1.x + v1.y) + (v1.z + v1.w));
#pragma unroll
    for (int o = 16; o; o >>= 1) sv += __shfl_xor_sync(0xffffffffu, sv, o);

    float s[7];
    float4 ebuf[7];
#pragma unroll
    for (int i = 0; i < 7; i++) {
        int l = w + 8 * i; int lc = (l < LLN) ? l : (LLN - 1);
        ebuf[i] = ((const float4*)(eb + (size_t)lc * BB * HH))[lane * 2];
    }
#pragma unroll
    for (int i = 0; i < 7; i++) {
        float r;
        r = frcp(fmaf(Q0.x, ebuf[i].x, 1.f)); s[i] = v0.x * r;
        r = frcp(fmaf(Q0.y, ebuf[i].y, 1.f)); s[i] = fmaf(v0.y, r, s[i]);
        r = frcp(fmaf(Q0.z, ebuf[i].z, 1.f)); s[i] = fmaf(v0.z, r, s[i]);
        r = frcp(fmaf(Q0.w, ebuf[i].w, 1.f)); s[i] = fmaf(v0.w, r, s[i]);
    }
#pragma unroll
    for (int i = 0; i < 7; i++) {
        int l = w + 8 * i; int lc = (l < LLN) ? l : (LLN - 1);
        ebuf[i] = ((const float4*)(eb + (size_t)lc * BB * HH))[lane * 2 + 1];
    }
#pragma unroll
    for (int i = 0; i < 7; i++) {
        float r;
        r = frcp(fmaf(Q1.x, ebuf[i].x, 1.f)); s[i] = fmaf(v1.x, r, s[i]);
        r = frcp(fmaf(Q1.y, ebuf[i].y, 1.f)); s[i] = fmaf(v1.y, r, s[i]);
        r = frcp(fmaf(Q1.z, ebuf[i].z, 1.f)); s[i] = fmaf(v1.z, r, s[i]);
        r = frcp(fmaf(Q1.w, ebuf[i].w, 1.f)); s[i] = fmaf(v1.w, r, s[i]);
    }
#pragma unroll
    for (int o = 16; o; o >>= 1)
#pragma unroll
        for (int i = 0; i < 7; i++) s[i] += __shfl_xor_sync(0xffffffffu, s[i], o);
    if (lane == 0) {
#pragma unroll
        for (int i = 0; i < 7; i++) {
            int l = w + 8 * i;
            if (l < LLN)
                sp[l] = g_mask[b * LLN + l] ? NEGV
                                            : (CEXPL * fast_tanh(fmaf(-2.f, s[i], sv)));
        }
    }
    __syncthreads();
    if (w == 0) {
        float a  = (lane < LLN) ? sp[lane] : -FLT_MAX;           int ia = lane;
        float bb = (lane + 32 < LLN) ? sp[lane + 32] : -FLT_MAX; int ib = lane + 32;
        float m; int mi;
        if (bb > a) { m = bb; mi = ib; } else { m = a; mi = ia; }
#pragma unroll
        for (int o = 16; o; o >>= 1) {
            float om = __shfl_xor_sync(0xffffffffu, m, o);
            int   oi = __shfl_xor_sync(0xffffffffu, mi, o);
            if (om > m || (om == m && oi < mi)) { m = om; mi = oi; }
        }
        float ssum = ((lane < LLN) ? __expf(a - m) : 0.f)
                   + ((lane + 32 < LLN) ? __expf(bb - m) : 0.f);
#pragma unroll
        for (int o = 16; o; o >>= 1) ssum += __shfl_xor_sync(0xffffffffu, ssum, o);
        if (lane == 0) { s_lse = m + __logf(ssum); s_idx = mi; }
    }
    __syncthreads();
    int idx = s_idx; float lse = s_lse;
    if (tid < LLN)
        out[((size_t)b * LLN + t) * LLN + tid] = sp[tid] - lse;
    if (tid == 0) {
        g_idx[b] = idx;                  // consumed by next step's k_cell
        g_mask[b * LLN + idx] = 1;       // mask for NEXT step
        int cnt = 0;
#pragma unroll
        for (int l = 0; l < LLN; l++) cnt += g_mask[b * LLN + l];
        if (cnt == LLN) g_mask[b * LLN + LLN - 1] = 0;   // ref's all-true reset
        if (wsel) sel_out[b * LLN + t] = (float)idx;
    }
    gdep_launch();                        // after all stores (idx, mask, out)
}

// -------------------------------- launch ----------------------------------
extern "C" void kernel_launch(void* const* d_in, const int* in_sizes, int n_in,
                              void* d_out, int out_size) {
    (void)in_sizes; (void)n_in;
    const float* dec  = (const float*)d_in[0];
    const float* emb  = (const float*)d_in[1];
    const float* h0   = (const float*)d_in[2];
    const float* c0   = (const float*)d_in[3];
    const float* ctx  = (const float*)d_in[4];
    const float* Wih  = (const float*)d_in[6];
    const float* Whh  = (const float*)d_in[7];
    const float* bih  = (const float*)d_in[8];
    const float* bhh  = (const float*)d_in[9];
    const float* glWq = (const float*)d_in[10];
    const float* glbq = (const float*)d_in[11];
    const float* glWr = (const float*)d_in[12];
    const float* glbr = (const float*)d_in[13];
    const float* glv  = (const float*)d_in[14];
    const float* ptWq = (const float*)d_in[15];
    const float* ptbq = (const float*)d_in[16];
    const float* ptWr = (const float*)d_in[17];
    const float* ptbr = (const float*)d_in[18];
    const float* ptv  = (const float*)d_in[19];
    float* out = (float*)d_out;

    float *pe_gl, *pe_pt, *ph0, *ph1, *pg, *pzero, *pGx, *pGx0, *pWc;
    float *pqgl0, *pqgl1, *pqpt0, *pqpt1;
    cudaGetSymbolAddress((void**)&pe_gl, g_e_gl);
    cudaGetSymbolAddress((void**)&pe_pt, g_e_pt);
    cudaGetSymbolAddress((void**)&ph0,   g_h0);
    cudaGetSymbolAddress((void**)&ph1,   g_h1);
    cudaGetSymbolAddress((void**)&pg,    g_g);
    cudaGetSymbolAddress((void**)&pzero, g_zero);
    cudaGetSymbolAddress((void**)&pGx,   g_Gx);
    cudaGetSymbolAddress((void**)&pGx0,  g_Gx0);
    cudaGetSymbolAddress((void**)&pWc,   g_Wc);
    cudaGetSymbolAddress((void**)&pqgl0, g_qgl0);
    cudaGetSymbolAddress((void**)&pqgl1, g_qgl1);
    cudaGetSymbolAddress((void**)&pqpt0, g_qpt0);
    cudaGetSymbolAddress((void**)&pqpt1, g_qpt1);

    // PDL launch config (programmatic stream serialization)
    cudaLaunchAttribute pdlAttr{};
    pdlAttr.id = cudaLaunchAttributeProgrammaticStreamSerialization;
    pdlAttr.val.programmaticStreamSerializationAllowed = 1;
    auto mkcfg = [&](dim3 g, dim3 b) {
        cudaLaunchConfig_t c{};
        c.gridDim = g; c.blockDim = b; c.dynamicSmemBytes = 0;
        c.stream = 0; c.attrs = &pdlAttr; c.numAttrs = 1;
        return c;
    };

    k_init<<<1024, 256>>>(h0, c0);
    k_prep_lstm<<<H4, 256>>>(Wih, Whh, bih, bhh);

    // Time-invariant projections WITH fused exp: E_gl, E_pt
    {
        GA a0{ctx, HH, glWr, HH, glbr, pe_gl};
        GA a1{ctx, HH, ptWr, HH, ptbr, pe_pt};
        cudaLaunchConfig_t c = mkcfg(dim3(HH / 64, (LLN * BB) / 128, 2), dim3(256));
        cudaLaunchKernelEx(&c, gemm_multi<128, 64, 16, 8, 4, 1>, a0, a1, (int)HH, (int)HH);
    }
    // Precompute x-part gates for ALL candidate inputs: Gx = emb @ Wc_x^T
    {
        GA a{emb, EE, pWc, KK2, pzero, pGx};
        cudaLaunchConfig_t c = mkcfg(dim3(H4 / 64, (LLN * BB) / 128, 1), dim3(256));
        cudaLaunchKernelEx(&c, gemm_multi<128, 64, 16, 8, 4, 0>, a, a, (int)H4, (int)EE);
    }
    // Gx0 = dec @ Wc_x^T (t=0 input)
    {
        GA a{dec, EE, pWc, KK2, pzero, pGx0};
        cudaLaunchConfig_t c = mkcfg(dim3(H4 / 64, BB / 128, 1), dim3(256));
        cudaLaunchKernelEx(&c, gemm_multi<128, 64, 16, 8, 4, 0>, a, a, (int)H4, (int)EE);
    }

    const size_t BLLL = (size_t)BB * LLN * LLN;
    const int wsel = (out_size >= (int)(BLLL + (size_t)BB * LLN)) ? 1 : 0;

    float* hb[2] = {ph0, ph1};
    for (int t = 0; t < LLN; t++) {
        float* hprev = hb[t & 1];
        float* hcur  = hb[(t + 1) & 1];
        // LSTM h-part gates, split-K x4 over K=256 -> g_G[0..3]
        {
            cudaLaunchConfig_t c = mkcfg(dim3(H4 / 64, BB / 64, KSPLIT), dim3(128));
            cudaLaunchKernelEx(&c, k_lstmH, (const float*)hprev);
        }
        // cell: h-partials + gathered Gx[idx] + bias -> nonlinearity -> hcur
        {
            cudaLaunchConfig_t c = mkcfg(dim3(BB), dim3(HH));
            cudaLaunchKernelEx(&c, k_cell, t, hcur);
        }
        // q_gl split-K x2 (bias in z=0; partials summed in k_attn_gl)
        {
            GA a0{hcur,       HH, glWq,       HH, glbq,  pqgl0};
            GA a1{hcur + 128, HH, glWq + 128, HH, pzero, pqgl1};
            cudaLaunchConfig_t c = mkcfg(dim3(HH / 64, BB / 32, 2), dim3(128));
            cudaLaunchKernelEx(&c, gemm_multi<32, 64, 16, 4, 4, 0>, a0, a1, (int)HH, 128);
        }
        // glimpse attention -> g
        {
            cudaLaunchConfig_t c = mkcfg(dim3(BB), dim3(HH));
            cudaLaunchKernelEx(&c, k_attn_gl, glv);
        }
        // q_pt split-K x2
        {
            GA a0{pg,       HH, ptWq,       HH, ptbq,  pqpt0};
            GA a1{pg + 128, HH, ptWq + 128, HH, pzero, pqpt1};
            cudaLaunchConfig_t c = mkcfg(dim3(HH / 64, BB / 32, 2), dim3(128));
            cudaLaunchKernelEx(&c, gemm_multi<32, 64, 16, 4, 4, 0>, a0, a1, (int)HH, 128);
        }
        // pointer attention: log_p -> out, argmax, idx/mask update
        {
            cudaLaunchConfig_t c = mkcfg(dim3(BB), dim3(HH));
            cudaLaunchKernelEx(&c, k_attn_pt, ptv, out, out + BLLL, t, wsel);
        }
    }
}